// round 1
// baseline (speedup 1.0000x reference)
#include <cuda_runtime.h>
#include <cstdint>
#include <cstddef>

// Problem constants
#define Bsz   64
#define Tlen  512
#define DIN   512
#define Hsz   1024
#define G4H   4096          // 4*H
#define NTOT  8192          // both directions' gates
#define MROWS 32768         // B*T

// ---------------------------------------------------------------------------
// Persistent scratch (static device globals; allocation at module load only)
// ---------------------------------------------------------------------------
// G[m][n]: m = b*T + t, n in [0,8192): [0,4096) fwd gates (i,f,g,o each 1024),
// [4096,8192) bwd gates. Bias (b_ih+b_hh) folded in.
__device__ float g_G[(size_t)MROWS * NTOT];          // 1.07 GB
__device__ float g_h[2][2][Bsz * Hsz];               // [parity][dir][b*H+h]
__device__ float g_c[2][Bsz * Hsz];                  // [dir][b*H+h]

// ---------------------------------------------------------------------------
// Zero the recurrent state (must run every launch: graph is replayed N times)
// ---------------------------------------------------------------------------
__global__ void zero_state_kernel() {
    int i = blockIdx.x * blockDim.x + threadIdx.x;
    if (i < Bsz * Hsz) {
        g_h[0][0][i] = 0.f;
        g_h[0][1][i] = 0.f;
        g_c[0][i]    = 0.f;
        g_c[1][i]    = 0.f;
    }
}

// ---------------------------------------------------------------------------
// Phase 1: G = X @ Wcat^T + bias      (M=32768, N=8192, K=512)
// BM=128, BN=64, BK=16, 256 threads, thread tile 8x4.
// ---------------------------------------------------------------------------
__global__ __launch_bounds__(256) void gemm_x_kernel(
    const float* __restrict__ X,
    const float* __restrict__ Wf, const float* __restrict__ Wb,
    const float* __restrict__ bihf, const float* __restrict__ bhhf,
    const float* __restrict__ bihb, const float* __restrict__ bhhb)
{
    __shared__ float As[128][17];
    __shared__ float Bs[64][17];

    const int m0  = blockIdx.y * 128;
    const int n0  = blockIdx.x * 64;
    const int tid = threadIdx.x;
    const int ty  = tid >> 4;   // 0..15 -> rows ty*8 .. ty*8+7
    const int tx  = tid & 15;   // cols tx + 16*c

    float acc[8][4];
#pragma unroll
    for (int r = 0; r < 8; r++)
#pragma unroll
        for (int c = 0; c < 4; c++) acc[r][c] = 0.f;

    for (int k0 = 0; k0 < DIN; k0 += 16) {
        // A tile: 128x16 floats = 512 float4, 2 per thread
#pragma unroll
        for (int i = 0; i < 2; i++) {
            int idx = tid * 2 + i;          // 0..511
            int row = idx >> 2;
            int c4  = (idx & 3) << 2;
            float4 v = *(const float4*)&X[(size_t)(m0 + row) * DIN + k0 + c4];
            As[row][c4 + 0] = v.x; As[row][c4 + 1] = v.y;
            As[row][c4 + 2] = v.z; As[row][c4 + 3] = v.w;
        }
        // B tile: 64x16 floats = 256 float4, 1 per thread
        {
            int row = tid >> 2;
            int c4  = (tid & 3) << 2;
            int n   = n0 + row;
            const float* Wp = (n < G4H) ? &Wf[(size_t)n * DIN]
                                        : &Wb[(size_t)(n - G4H) * DIN];
            float4 v = *(const float4*)&Wp[k0 + c4];
            Bs[row][c4 + 0] = v.x; Bs[row][c4 + 1] = v.y;
            Bs[row][c4 + 2] = v.z; Bs[row][c4 + 3] = v.w;
        }
        __syncthreads();
#pragma unroll
        for (int kk = 0; kk < 16; kk++) {
            float a[8], b[4];
#pragma unroll
            for (int r = 0; r < 8; r++) a[r] = As[ty * 8 + r][kk];
#pragma unroll
            for (int c = 0; c < 4; c++) b[c] = Bs[tx + 16 * c][kk];
#pragma unroll
            for (int r = 0; r < 8; r++)
#pragma unroll
                for (int c = 0; c < 4; c++) acc[r][c] += a[r] * b[c];
        }
        __syncthreads();
    }

#pragma unroll
    for (int c = 0; c < 4; c++) {
        int n = n0 + tx + 16 * c;
        float bias = (n < G4H) ? (bihf[n] + bhhf[n])
                               : (bihb[n - G4H] + bhhb[n - G4H]);
#pragma unroll
        for (int r = 0; r < 8; r++) {
            g_G[(size_t)(m0 + ty * 8 + r) * NTOT + n] = acc[r][c] + bias;
        }
    }
}

// ---------------------------------------------------------------------------
// Phase 2: one LSTM timestep, both directions fused.
// grid = 128 blocks: dir = bx>>6, h-tile of 16 = (bx&63)*16
// block = 128 threads: ty=tid>>4 (8 batch rows each), tx=tid&15 (h column)
// Each block computes gates[64 batch x (4 gates x 16 h)] = h_prev @ W_hh^T
// then does the pointwise cell update in-register.
// ---------------------------------------------------------------------------
__global__ __launch_bounds__(128) void lstm_step_kernel(
    const float* __restrict__ Whhf, const float* __restrict__ Whhb,
    float* __restrict__ out, int s, int par)
{
    __shared__ float As[64][17];   // [batch][kk]
    __shared__ float Bs[64][17];   // [g*16 + hcol][kk]

    const int dir = blockIdx.x >> 6;
    const int hb  = (blockIdx.x & 63) << 4;
    const int tid = threadIdx.x;
    const int ty  = tid >> 4;      // 0..7
    const int tx  = tid & 15;      // 0..15

    const float* __restrict__ W     = dir ? Whhb : Whhf;
    const float* __restrict__ hprev = g_h[par][dir];

    float acc[8][4];
#pragma unroll
    for (int r = 0; r < 8; r++)
#pragma unroll
        for (int g = 0; g < 4; g++) acc[r][g] = 0.f;

    for (int k0 = 0; k0 < Hsz; k0 += 16) {
#pragma unroll
        for (int i = 0; i < 2; i++) {
            int idx = tid * 2 + i;          // 0..255 float4 slots
            int row = idx >> 2;             // 0..63
            int c4  = (idx & 3) << 2;
            // A: h_prev[batch=row][k0+c4..]
            float4 v = *(const float4*)&hprev[row * Hsz + k0 + c4];
            As[row][c4 + 0] = v.x; As[row][c4 + 1] = v.y;
            As[row][c4 + 2] = v.z; As[row][c4 + 3] = v.w;
            // B: W_hh[g*1024 + hb + j][k0+c4..]
            int g = row >> 4, j = row & 15;
            float4 w = *(const float4*)&W[(size_t)((g << 10) + hb + j) * Hsz + k0 + c4];
            Bs[row][c4 + 0] = w.x; Bs[row][c4 + 1] = w.y;
            Bs[row][c4 + 2] = w.z; Bs[row][c4 + 3] = w.w;
        }
        __syncthreads();
#pragma unroll
        for (int kk = 0; kk < 16; kk++) {
            float a[8], b[4];
#pragma unroll
            for (int r = 0; r < 8; r++) a[r] = As[ty * 8 + r][kk];
#pragma unroll
            for (int g = 0; g < 4; g++) b[g] = Bs[g * 16 + tx][kk];
#pragma unroll
            for (int r = 0; r < 8; r++)
#pragma unroll
                for (int g = 0; g < 4; g++) acc[r][g] += a[r] * b[g];
        }
        __syncthreads();
    }

    // Pointwise LSTM update
    const int t_in = dir ? (Tlen - 1 - s) : s;   // bwd scan consumes reversed x
    float* __restrict__ hnew = g_h[par ^ 1][dir];
    float* __restrict__ cst  = g_c[dir];
    const int h = hb + tx;

#pragma unroll
    for (int r = 0; r < 8; r++) {
        int b = ty * 8 + r;
        const float* gx = &g_G[((size_t)b * Tlen + t_in) * NTOT + dir * G4H];
        float gi = acc[r][0] + gx[h];
        float gf = acc[r][1] + gx[Hsz + h];
        float gg = acc[r][2] + gx[2 * Hsz + h];
        float go = acc[r][3] + gx[3 * Hsz + h];

        float si = 1.f / (1.f + expf(-gi));
        float sf = 1.f / (1.f + expf(-gf));
        float so = 1.f / (1.f + expf(-go));
        float tg = tanhf(gg);

        int ci = b * Hsz + h;
        float cn = sf * cst[ci] + si * tg;
        cst[ci] = cn;
        float hn = so * tanhf(cn);
        hnew[ci] = hn;
        // hidden_states[b][s][dir*H + h]  (bwd stored in traversal order)
        out[((size_t)b * Tlen + s) * (2 * Hsz) + dir * Hsz + h] = hn;
    }
}

// ---------------------------------------------------------------------------
// Phase 3: initial_hiddens = tanh([hT_f|hT_b] @ fh_W^T + fh_b)
//          initial_cells   = tanh([cT_f|cT_b] @ fc_W^T + fc_b)
// M=64, N=1024, K=2048, two matrices (blockIdx.y selects).
// ---------------------------------------------------------------------------
__global__ __launch_bounds__(128) void proj_kernel(
    const float* __restrict__ fhW, const float* __restrict__ fhb,
    const float* __restrict__ fcW, const float* __restrict__ fcb,
    float* __restrict__ out2)
{
    __shared__ float As[64][17];
    __shared__ float Bs[64][17];

    const int which = blockIdx.y;   // 0: hiddens (fh), 1: cells (fc)
    const float* __restrict__ W    = which ? fcW : fhW;
    const float* __restrict__ bias = which ? fcb : fhb;
    const float* __restrict__ src0 = which ? g_c[0] : g_h[0][0];
    const float* __restrict__ src1 = which ? g_c[1] : g_h[0][1];

    const int d0  = blockIdx.x * 64;
    const int tid = threadIdx.x;
    const int ty  = tid >> 4;
    const int tx  = tid & 15;

    float acc[8][4];
#pragma unroll
    for (int r = 0; r < 8; r++)
#pragma unroll
        for (int c = 0; c < 4; c++) acc[r][c] = 0.f;

    for (int k0 = 0; k0 < 2 * Hsz; k0 += 16) {
#pragma unroll
        for (int i = 0; i < 2; i++) {
            int idx = tid * 2 + i;
            int row = idx >> 2;
            int c4  = (idx & 3) << 2;
            int k   = k0 + c4;
            const float* sp = (k < Hsz) ? &src0[row * Hsz + k]
                                        : &src1[row * Hsz + k - Hsz];
            float4 v = *(const float4*)sp;
            As[row][c4 + 0] = v.x; As[row][c4 + 1] = v.y;
            As[row][c4 + 2] = v.z; As[row][c4 + 3] = v.w;

            float4 w = *(const float4*)&W[(size_t)(d0 + row) * (2 * Hsz) + k0 + c4];
            Bs[row][c4 + 0] = w.x; Bs[row][c4 + 1] = w.y;
            Bs[row][c4 + 2] = w.z; Bs[row][c4 + 3] = w.w;
        }
        __syncthreads();
#pragma unroll
        for (int kk = 0; kk < 16; kk++) {
            float a[8], b[4];
#pragma unroll
            for (int r = 0; r < 8; r++) a[r] = As[ty * 8 + r][kk];
#pragma unroll
            for (int c = 0; c < 4; c++) b[c] = Bs[tx + 16 * c][kk];
#pragma unroll
            for (int r = 0; r < 8; r++)
#pragma unroll
                for (int c = 0; c < 4; c++) acc[r][c] += a[r] * b[c];
        }
        __syncthreads();
    }

#pragma unroll
    for (int c = 0; c < 4; c++) {
        int d = d0 + tx + 16 * c;
        float bv = bias[d];
#pragma unroll
        for (int r = 0; r < 8; r++) {
            int b = ty * 8 + r;
            out2[(size_t)which * (Bsz * Hsz) + b * Hsz + d] = tanhf(acc[r][c] + bv);
        }
    }
}

// ---------------------------------------------------------------------------
// Launch
// ---------------------------------------------------------------------------
extern "C" void kernel_launch(void* const* d_in, const int* in_sizes, int n_in,
                              void* d_out, int out_size)
{
    const float* X    = (const float*)d_in[0];
    const float* Wihf = (const float*)d_in[1];
    const float* Whhf = (const float*)d_in[2];
    const float* bihf = (const float*)d_in[3];
    const float* bhhf = (const float*)d_in[4];
    const float* Wihb = (const float*)d_in[5];
    const float* Whhb = (const float*)d_in[6];
    const float* bihb = (const float*)d_in[7];
    const float* bhhb = (const float*)d_in[8];
    const float* fcW  = (const float*)d_in[9];
    const float* fcb  = (const float*)d_in[10];
    const float* fhW  = (const float*)d_in[11];
    const float* fhb  = (const float*)d_in[12];
    float* out = (float*)d_out;

    // Reset recurrent state (graph is replayed; state must not persist)
    zero_state_kernel<<<(Bsz * Hsz + 255) / 256, 256>>>();

    // Phase 1: input projection for all timesteps, both directions
    gemm_x_kernel<<<dim3(NTOT / 64, MROWS / 128), 256>>>(
        X, Wihf, Wihb, bihf, bhhf, bihb, bhhb);

    // Phase 2: 512 sequential steps, fwd+bwd fused per launch
    for (int s = 0; s < Tlen; s++) {
        lstm_step_kernel<<<128, 128>>>(Whhf, Whhb, out, s, s & 1);
    }

    // Phase 3: decoder-init projections (after hidden_states block in d_out)
    proj_kernel<<<dim3(Hsz / 64, 2), 128>>>(
        fhW, fhb, fcW, fcb, out + (size_t)Bsz * Tlen * 2 * Hsz);
}

// round 2
// speedup vs baseline: 1.4281x; 1.4281x over previous
#include <cuda_runtime.h>
#include <cstdint>
#include <cstddef>

#define Bsz   64
#define Tlen  512
#define DIN   512
#define Hsz   1024
#define G4H   4096
#define NTOT  8192
#define MROWS 32768

// ---------------------------------------------------------------------------
// Persistent scratch
// ---------------------------------------------------------------------------
__device__ float g_G[(size_t)MROWS * NTOT];          // gate preactivations (x-part + bias)
__device__ float g_h[2][2][Bsz * Hsz];               // [parity][dir]
__device__ float g_c[2][Bsz * Hsz];                  // [dir]

__global__ void zero_state_kernel() {
    int i = blockIdx.x * blockDim.x + threadIdx.x;
    if (i < Bsz * Hsz) {
        g_h[0][0][i] = 0.f;
        g_h[0][1][i] = 0.f;
        g_c[0][i]    = 0.f;
        g_c[1][i]    = 0.f;
    }
}

// ---------------------------------------------------------------------------
// tf32 MMA helpers
// ---------------------------------------------------------------------------
__device__ __forceinline__ uint32_t f2tf32(float x) {
    uint32_t r;
    asm("cvt.rna.tf32.f32 %0, %1;" : "=r"(r) : "f"(x));
    return r;
}

__device__ __forceinline__ void mma_tf32(float* c, const uint32_t* a, const uint32_t* b) {
    asm volatile(
        "mma.sync.aligned.m16n8k8.row.col.f32.tf32.tf32.f32 "
        "{%0,%1,%2,%3},{%4,%5,%6,%7},{%8,%9},{%0,%1,%2,%3};"
        : "+f"(c[0]), "+f"(c[1]), "+f"(c[2]), "+f"(c[3])
        : "r"(a[0]), "r"(a[1]), "r"(a[2]), "r"(a[3]), "r"(b[0]), "r"(b[1]));
}

// Shared 64x64 tf32 tile compute:
// 256 threads = 8 warps; warp_m = wid&1 (2 x 32 rows), warp_n = wid>>1 (4 x 16 cols)
// acc[mf][nf][4] covers (warp_m*32 + mf*16) x (warp_n*16 + nf*8)
#define TILE_MMA_STEP(As, Bs, acc, kk)                                          \
    {                                                                           \
        uint32_t a_[2][4], b_[2][2];                                            \
        _Pragma("unroll")                                                       \
        for (int mf = 0; mf < 2; mf++) {                                        \
            int r = warp_m * 32 + mf * 16 + groupID;                            \
            a_[mf][0] = As[r][(kk) + tig];                                      \
            a_[mf][1] = As[r + 8][(kk) + tig];                                  \
            a_[mf][2] = As[r][(kk) + tig + 4];                                  \
            a_[mf][3] = As[r + 8][(kk) + tig + 4];                              \
        }                                                                       \
        _Pragma("unroll")                                                       \
        for (int nf = 0; nf < 2; nf++) {                                        \
            int n = warp_n * 16 + nf * 8 + groupID;                             \
            b_[nf][0] = Bs[n][(kk) + tig];                                      \
            b_[nf][1] = Bs[n][(kk) + tig + 4];                                  \
        }                                                                       \
        _Pragma("unroll")                                                       \
        for (int mf = 0; mf < 2; mf++)                                          \
            _Pragma("unroll")                                                   \
            for (int nf = 0; nf < 2; nf++)                                      \
                mma_tf32(acc[mf][nf], a_[mf], b_[nf]);                          \
    }

// ---------------------------------------------------------------------------
// Phase 1: G = X @ [Wf|Wb]^T + bias   (M=32768, N=8192, K=512), tf32 MMA
// Tile 64x64, BK=32, 256 threads.
// ---------------------------------------------------------------------------
__global__ __launch_bounds__(256) void gemm_x_mma(
    const float* __restrict__ X,
    const float* __restrict__ Wf, const float* __restrict__ Wb,
    const float* __restrict__ bihf, const float* __restrict__ bhhf,
    const float* __restrict__ bihb, const float* __restrict__ bhhb)
{
    __shared__ uint32_t As[64][33];
    __shared__ uint32_t Bs[64][33];

    const int n0  = blockIdx.x * 64;
    const int m0  = blockIdx.y * 64;
    const int tid = threadIdx.x;
    const int wid = tid >> 5, lane = tid & 31;
    const int warp_m = wid & 1, warp_n = wid >> 1;
    const int groupID = lane >> 2, tig = lane & 3;

    float acc[2][2][4];
#pragma unroll
    for (int mf = 0; mf < 2; mf++)
#pragma unroll
        for (int nf = 0; nf < 2; nf++)
#pragma unroll
            for (int i = 0; i < 4; i++) acc[mf][nf][i] = 0.f;

    for (int k0 = 0; k0 < DIN; k0 += 32) {
        // A fill: 64x32 = 512 float4, 2 per thread
#pragma unroll
        for (int i = 0; i < 2; i++) {
            int idx = tid * 2 + i;
            int row = idx >> 3;
            int c4  = (idx & 7) << 2;
            float4 v = *(const float4*)&X[(size_t)(m0 + row) * DIN + k0 + c4];
            As[row][c4 + 0] = f2tf32(v.x); As[row][c4 + 1] = f2tf32(v.y);
            As[row][c4 + 2] = f2tf32(v.z); As[row][c4 + 3] = f2tf32(v.w);
        }
        // B fill
#pragma unroll
        for (int i = 0; i < 2; i++) {
            int idx = tid * 2 + i;
            int row = idx >> 3;
            int c4  = (idx & 7) << 2;
            int n   = n0 + row;
            const float* Wp = (n < G4H) ? &Wf[(size_t)n * DIN]
                                        : &Wb[(size_t)(n - G4H) * DIN];
            float4 v = *(const float4*)&Wp[k0 + c4];
            Bs[row][c4 + 0] = f2tf32(v.x); Bs[row][c4 + 1] = f2tf32(v.y);
            Bs[row][c4 + 2] = f2tf32(v.z); Bs[row][c4 + 3] = f2tf32(v.w);
        }
        __syncthreads();
#pragma unroll
        for (int kk = 0; kk < 32; kk += 8) TILE_MMA_STEP(As, Bs, acc, kk)
        __syncthreads();
    }

    // Epilogue: add bias, store float2 pairs
#pragma unroll
    for (int nf = 0; nf < 2; nf++) {
        int c0 = warp_n * 16 + nf * 8 + 2 * tig;
        int n  = n0 + c0;
        float bias0, bias1;
        if (n < G4H) { bias0 = bihf[n] + bhhf[n]; bias1 = bihf[n + 1] + bhhf[n + 1]; }
        else         { bias0 = bihb[n - G4H] + bhhb[n - G4H];
                       bias1 = bihb[n + 1 - G4H] + bhhb[n + 1 - G4H]; }
#pragma unroll
        for (int mf = 0; mf < 2; mf++) {
            int r0 = m0 + warp_m * 32 + mf * 16 + groupID;
            float2 v0 = make_float2(acc[mf][nf][0] + bias0, acc[mf][nf][1] + bias1);
            float2 v1 = make_float2(acc[mf][nf][2] + bias0, acc[mf][nf][3] + bias1);
            *(float2*)&g_G[(size_t)r0 * NTOT + n]       = v0;
            *(float2*)&g_G[(size_t)(r0 + 8) * NTOT + n] = v1;
        }
    }
}

// ---------------------------------------------------------------------------
// Phase 2: one LSTM timestep (both dirs), tf32 MMA.
// grid=128: dir = bx>>6, h-tile = (bx&63)*16. N-cols of tile = gate*16 + j.
// Tile M=64 (batch) x N=64 (4 gates x 16 h), K=1024.
// ---------------------------------------------------------------------------
__global__ __launch_bounds__(256) void lstm_step_mma(
    const float* __restrict__ Whhf, const float* __restrict__ Whhb,
    float* __restrict__ out, int s, int par)
{
    __shared__ uint32_t As[64][33];
    __shared__ uint32_t Bs[64][33];
    __shared__ float    Gt[64][65];

    const int dir = blockIdx.x >> 6;
    const int hb  = (blockIdx.x & 63) << 4;
    const int tid = threadIdx.x;
    const int wid = tid >> 5, lane = tid & 31;
    const int warp_m = wid & 1, warp_n = wid >> 1;
    const int groupID = lane >> 2, tig = lane & 3;

    const float* __restrict__ W     = dir ? Whhb : Whhf;
    const float* __restrict__ hprev = g_h[par][dir];

    float acc[2][2][4];
#pragma unroll
    for (int mf = 0; mf < 2; mf++)
#pragma unroll
        for (int nf = 0; nf < 2; nf++)
#pragma unroll
            for (int i = 0; i < 4; i++) acc[mf][nf][i] = 0.f;

    for (int k0 = 0; k0 < Hsz; k0 += 32) {
#pragma unroll
        for (int i = 0; i < 2; i++) {
            int idx = tid * 2 + i;
            int row = idx >> 3;
            int c4  = (idx & 7) << 2;
            // A: h_prev[batch=row][k]
            float4 v = *(const float4*)&hprev[row * Hsz + k0 + c4];
            As[row][c4 + 0] = f2tf32(v.x); As[row][c4 + 1] = f2tf32(v.y);
            As[row][c4 + 2] = f2tf32(v.z); As[row][c4 + 3] = f2tf32(v.w);
            // B: W[(g<<10) + hb + j][k], row = g*16 + j
            int g = row >> 4, j = row & 15;
            float4 w = *(const float4*)&W[(size_t)((g << 10) + hb + j) * Hsz + k0 + c4];
            Bs[row][c4 + 0] = f2tf32(w.x); Bs[row][c4 + 1] = f2tf32(w.y);
            Bs[row][c4 + 2] = f2tf32(w.z); Bs[row][c4 + 3] = f2tf32(w.w);
        }
        __syncthreads();
#pragma unroll
        for (int kk = 0; kk < 32; kk += 8) TILE_MMA_STEP(As, Bs, acc, kk)
        __syncthreads();
    }

    // Scatter accumulators to smem gate tile: Gt[batch][g*16+j]
#pragma unroll
    for (int mf = 0; mf < 2; mf++) {
        int r0 = warp_m * 32 + mf * 16 + groupID;
#pragma unroll
        for (int nf = 0; nf < 2; nf++) {
            int c0 = warp_n * 16 + nf * 8 + 2 * tig;
            Gt[r0][c0]     = acc[mf][nf][0];
            Gt[r0][c0 + 1] = acc[mf][nf][1];
            Gt[r0 + 8][c0]     = acc[mf][nf][2];
            Gt[r0 + 8][c0 + 1] = acc[mf][nf][3];
        }
    }
    __syncthreads();

    // Pointwise LSTM cell update (fp32)
    const int t_in = dir ? (Tlen - 1 - s) : s;
    float* __restrict__ hnew = g_h[par ^ 1][dir];
    float* __restrict__ cst  = g_c[dir];

    for (int i = tid; i < Bsz * 16; i += 256) {
        int b = i >> 4;
        int j = i & 15;
        int h = hb + j;
        const float* gx = &g_G[((size_t)b * Tlen + t_in) * NTOT + dir * G4H];
        float gi = Gt[b][j]      + gx[h];
        float gf = Gt[b][16 + j] + gx[Hsz + h];
        float gg = Gt[b][32 + j] + gx[2 * Hsz + h];
        float go = Gt[b][48 + j] + gx[3 * Hsz + h];

        float si = 1.f / (1.f + expf(-gi));
        float sf = 1.f / (1.f + expf(-gf));
        float so = 1.f / (1.f + expf(-go));
        float tg = tanhf(gg);

        int ci = b * Hsz + h;
        float cn = sf * cst[ci] + si * tg;
        cst[ci] = cn;
        float hn = so * tanhf(cn);
        hnew[ci] = hn;
        out[((size_t)b * Tlen + s) * (2 * Hsz) + dir * Hsz + h] = hn;
    }
}

// ---------------------------------------------------------------------------
// Phase 3: decoder-init projections (fp32, tiny)
// ---------------------------------------------------------------------------
__global__ __launch_bounds__(128) void proj_kernel(
    const float* __restrict__ fhW, const float* __restrict__ fhb,
    const float* __restrict__ fcW, const float* __restrict__ fcb,
    float* __restrict__ out2)
{
    __shared__ float As[64][17];
    __shared__ float Bs[64][17];

    const int which = blockIdx.y;
    const float* __restrict__ W    = which ? fcW : fhW;
    const float* __restrict__ bias = which ? fcb : fhb;
    const float* __restrict__ src0 = which ? g_c[0] : g_h[0][0];
    const float* __restrict__ src1 = which ? g_c[1] : g_h[0][1];

    const int d0  = blockIdx.x * 64;
    const int tid = threadIdx.x;
    const int ty  = tid >> 4;
    const int tx  = tid & 15;

    float acc[8][4];
#pragma unroll
    for (int r = 0; r < 8; r++)
#pragma unroll
        for (int c = 0; c < 4; c++) acc[r][c] = 0.f;

    for (int k0 = 0; k0 < 2 * Hsz; k0 += 16) {
#pragma unroll
        for (int i = 0; i < 2; i++) {
            int idx = tid * 2 + i;
            int row = idx >> 2;
            int c4  = (idx & 3) << 2;
            int k   = k0 + c4;
            const float* sp = (k < Hsz) ? &src0[row * Hsz + k]
                                        : &src1[row * Hsz + k - Hsz];
            float4 v = *(const float4*)sp;
            As[row][c4 + 0] = v.x; As[row][c4 + 1] = v.y;
            As[row][c4 + 2] = v.z; As[row][c4 + 3] = v.w;

            float4 w = *(const float4*)&W[(size_t)(d0 + row) * (2 * Hsz) + k0 + c4];
            Bs[row][c4 + 0] = w.x; Bs[row][c4 + 1] = w.y;
            Bs[row][c4 + 2] = w.z; Bs[row][c4 + 3] = w.w;
        }
        __syncthreads();
#pragma unroll
        for (int kk = 0; kk < 16; kk++) {
            float a[8], b[4];
#pragma unroll
            for (int r = 0; r < 8; r++) a[r] = As[ty * 8 + r][kk];
#pragma unroll
            for (int c = 0; c < 4; c++) b[c] = Bs[tx + 16 * c][kk];
#pragma unroll
            for (int r = 0; r < 8; r++)
#pragma unroll
                for (int c = 0; c < 4; c++) acc[r][c] += a[r] * b[c];
        }
        __syncthreads();
    }

#pragma unroll
    for (int c = 0; c < 4; c++) {
        int d = d0 + tx + 16 * c;
        float bv = bias[d];
#pragma unroll
        for (int r = 0; r < 8; r++) {
            int b = ty * 8 + r;
            out2[(size_t)which * (Bsz * Hsz) + b * Hsz + d] = tanhf(acc[r][c] + bv);
        }
    }
}

// ---------------------------------------------------------------------------
// Launch
// ---------------------------------------------------------------------------
extern "C" void kernel_launch(void* const* d_in, const int* in_sizes, int n_in,
                              void* d_out, int out_size)
{
    const float* X    = (const float*)d_in[0];
    const float* Wihf = (const float*)d_in[1];
    const float* Whhf = (const float*)d_in[2];
    const float* bihf = (const float*)d_in[3];
    const float* bhhf = (const float*)d_in[4];
    const float* Wihb = (const float*)d_in[5];
    const float* Whhb = (const float*)d_in[6];
    const float* bihb = (const float*)d_in[7];
    const float* bhhb = (const float*)d_in[8];
    const float* fcW  = (const float*)d_in[9];
    const float* fcb  = (const float*)d_in[10];
    const float* fhW  = (const float*)d_in[11];
    const float* fhb  = (const float*)d_in[12];
    float* out = (float*)d_out;

    zero_state_kernel<<<(Bsz * Hsz + 255) / 256, 256>>>();

    gemm_x_mma<<<dim3(NTOT / 64, MROWS / 64), 256>>>(
        X, Wihf, Wihb, bihf, bhhf, bihb, bhhb);

    for (int s = 0; s < Tlen; s++) {
        lstm_step_mma<<<128, 256>>>(Whhf, Whhb, out, s, s & 1);
    }

    proj_kernel<<<dim3(Hsz / 64, 2), 128>>>(
        fhW, fhb, fcW, fcb, out + (size_t)Bsz * Tlen * 2 * Hsz);
}

// round 3
// speedup vs baseline: 2.7395x; 1.9183x over previous
#include <cuda_runtime.h>
#include <cstdint>
#include <cstddef>

#define Bsz   64
#define Tlen  512
#define DIN   512
#define Hsz   1024
#define G4H   4096
#define NTOT  8192
#define MROWS 32768

// ---------------------------------------------------------------------------
// Persistent scratch
// ---------------------------------------------------------------------------
__device__ float g_G[(size_t)MROWS * NTOT];
__device__ float g_h[2][2][Bsz * Hsz];
__device__ float g_c[2][Bsz * Hsz];

__global__ void zero_state_kernel() {
    int i = blockIdx.x * blockDim.x + threadIdx.x;
    if (i < Bsz * Hsz) {
        g_h[0][0][i] = 0.f;
        g_h[0][1][i] = 0.f;
        g_c[0][i]    = 0.f;
        g_c[1][i]    = 0.f;
    }
}

// ---------------------------------------------------------------------------
// MMA + cp.async helpers
// ---------------------------------------------------------------------------
__device__ __forceinline__ uint32_t f2tf32(float x) {
    uint32_t r;
    asm("cvt.rna.tf32.f32 %0, %1;" : "=r"(r) : "f"(x));
    return r;
}

__device__ __forceinline__ void mma_tf32(float* c, const uint32_t* a, const uint32_t* b) {
    asm volatile(
        "mma.sync.aligned.m16n8k8.row.col.f32.tf32.tf32.f32 "
        "{%0,%1,%2,%3},{%4,%5,%6,%7},{%8,%9},{%0,%1,%2,%3};"
        : "+f"(c[0]), "+f"(c[1]), "+f"(c[2]), "+f"(c[3])
        : "r"(a[0]), "r"(a[1]), "r"(a[2]), "r"(a[3]), "r"(b[0]), "r"(b[1]));
}

__device__ __forceinline__ void cp16(float* smem, const float* g) {
    uint32_t sa = (uint32_t)__cvta_generic_to_shared(smem);
    asm volatile("cp.async.ca.shared.global [%0], [%1], 16;" :: "r"(sa), "l"(g));
}
#define CP_COMMIT() asm volatile("cp.async.commit_group;")
#define CP_WAIT0()  asm volatile("cp.async.wait_group 0;")

// smem: 2 stages x (A 64x32 + B 64x32) floats, row stride 36 (16B-aligned rows,
// conflict-free fragment loads). Total 36,864 B. Gate tile overlays stage mem.
#define SSTRIDE 36
#define STAGEF  (64 * SSTRIDE)          // floats per tile per stage
#define ASF(buf, s, r, c) buf[((s) * 64 + (r)) * SSTRIDE + (c)]
#define BSF(buf, s, r, c) buf[2 * STAGEF + ((s) * 64 + (r)) * SSTRIDE + (c)]

// Warp-tile compute on stage st: 8 warps, warp_m = wid&1, warp_n = wid>>1,
// acc[mf][nf][4] covers rows warp_m*32+mf*16(+8) x cols warp_n*16+nf*8.
#define TILE_COMPUTE(buf, st)                                                    \
    _Pragma("unroll")                                                            \
    for (int kk = 0; kk < 32; kk += 8) {                                         \
        uint32_t a_[2][4], b_[2][2];                                             \
        _Pragma("unroll")                                                        \
        for (int mf = 0; mf < 2; mf++) {                                         \
            int r = warp_m * 32 + mf * 16 + groupID;                             \
            a_[mf][0] = f2tf32(ASF(buf, st, r,     kk + tig));                   \
            a_[mf][1] = f2tf32(ASF(buf, st, r + 8, kk + tig));                   \
            a_[mf][2] = f2tf32(ASF(buf, st, r,     kk + tig + 4));               \
            a_[mf][3] = f2tf32(ASF(buf, st, r + 8, kk + tig + 4));               \
        }                                                                        \
        _Pragma("unroll")                                                        \
        for (int nf = 0; nf < 2; nf++) {                                         \
            int n = warp_n * 16 + nf * 8 + groupID;                              \
            b_[nf][0] = f2tf32(BSF(buf, st, n, kk + tig));                       \
            b_[nf][1] = f2tf32(BSF(buf, st, n, kk + tig + 4));                   \
        }                                                                        \
        _Pragma("unroll")                                                        \
        for (int mf = 0; mf < 2; mf++)                                           \
            _Pragma("unroll")                                                    \
            for (int nf = 0; nf < 2; nf++)                                       \
                mma_tf32(acc[mf][nf], a_[mf], b_[nf]);                           \
    }

// ---------------------------------------------------------------------------
// Phase 1: G = X @ [Wf|Wb]^T + bias  (M=32768, N=8192, K=512), pipelined
// ---------------------------------------------------------------------------
__global__ __launch_bounds__(256) void gemm_x_mma(
    const float* __restrict__ X,
    const float* __restrict__ Wf, const float* __restrict__ Wb,
    const float* __restrict__ bihf, const float* __restrict__ bhhf,
    const float* __restrict__ bihb, const float* __restrict__ bhhb)
{
    __shared__ float sbuf[4 * STAGEF];

    const int n0  = blockIdx.x * 64;
    const int m0  = blockIdx.y * 64;
    const int tid = threadIdx.x;
    const int wid = tid >> 5, lane = tid & 31;
    const int warp_m = wid & 1, warp_n = wid >> 1;
    const int groupID = lane >> 2, tig = lane & 3;

    // per-thread load coords (2 x 16B per tile per stage)
    const int r0l = (tid * 2) >> 3,      c0l = ((tid * 2) & 7) << 2;
    const int r1l = (tid * 2 + 1) >> 3,  c1l = ((tid * 2 + 1) & 7) << 2;
    const float* WB0 = (n0 + r0l < G4H) ? &Wf[(size_t)(n0 + r0l) * DIN]
                                        : &Wb[(size_t)(n0 + r0l - G4H) * DIN];
    const float* WB1 = (n0 + r1l < G4H) ? &Wf[(size_t)(n0 + r1l) * DIN]
                                        : &Wb[(size_t)(n0 + r1l - G4H) * DIN];

    float acc[2][2][4];
#pragma unroll
    for (int mf = 0; mf < 2; mf++)
#pragma unroll
        for (int nf = 0; nf < 2; nf++)
#pragma unroll
            for (int i = 0; i < 4; i++) acc[mf][nf][i] = 0.f;

#define P1_LOAD(st, k0)                                                          \
    {                                                                            \
        cp16(&ASF(sbuf, st, r0l, c0l), &X[(size_t)(m0 + r0l) * DIN + (k0) + c0l]); \
        cp16(&BSF(sbuf, st, r0l, c0l), &WB0[(k0) + c0l]);                        \
        cp16(&ASF(sbuf, st, r1l, c1l), &X[(size_t)(m0 + r1l) * DIN + (k0) + c1l]); \
        cp16(&BSF(sbuf, st, r1l, c1l), &WB1[(k0) + c1l]);                        \
        CP_COMMIT();                                                             \
    }

    P1_LOAD(0, 0)
    const int NIT = DIN / 32;   // 16
    for (int it = 0; it < NIT; it++) {
        CP_WAIT0();
        __syncthreads();
        if (it + 1 < NIT) P1_LOAD((it + 1) & 1, (it + 1) * 32)
        TILE_COMPUTE(sbuf, it & 1)
        __syncthreads();
    }

#pragma unroll
    for (int nf = 0; nf < 2; nf++) {
        int c0 = warp_n * 16 + nf * 8 + 2 * tig;
        int n  = n0 + c0;
        float bias0, bias1;
        if (n < G4H) { bias0 = bihf[n] + bhhf[n]; bias1 = bihf[n + 1] + bhhf[n + 1]; }
        else         { bias0 = bihb[n - G4H] + bhhb[n - G4H];
                       bias1 = bihb[n + 1 - G4H] + bhhb[n + 1 - G4H]; }
#pragma unroll
        for (int mf = 0; mf < 2; mf++) {
            int r0 = m0 + warp_m * 32 + mf * 16 + groupID;
            float2 v0 = make_float2(acc[mf][nf][0] + bias0, acc[mf][nf][1] + bias1);
            float2 v1 = make_float2(acc[mf][nf][2] + bias0, acc[mf][nf][3] + bias1);
            *(float2*)&g_G[(size_t)r0 * NTOT + n]       = v0;
            *(float2*)&g_G[(size_t)(r0 + 8) * NTOT + n] = v1;
        }
    }
}

// ---------------------------------------------------------------------------
// Phase 2: one LSTM timestep (both dirs), pipelined tf32 MMA.
// grid=128: dir = bx>>6, h-tile = (bx&63)*16. Tile M=64 x N=64(4g x 16h), K=1024.
// ---------------------------------------------------------------------------
__global__ __launch_bounds__(256) void lstm_step_mma(
    const float* __restrict__ Whhf, const float* __restrict__ Whhb,
    float* __restrict__ out, int s, int par)
{
    __shared__ float sbuf[4 * STAGEF];

    const int dir = blockIdx.x >> 6;
    const int hb  = (blockIdx.x & 63) << 4;
    const int tid = threadIdx.x;
    const int wid = tid >> 5, lane = tid & 31;
    const int warp_m = wid & 1, warp_n = wid >> 1;
    const int groupID = lane >> 2, tig = lane & 3;

    const float* __restrict__ W     = dir ? Whhb : Whhf;
    const float* __restrict__ hprev = g_h[par][dir];

    const int r0l = (tid * 2) >> 3,      c0l = ((tid * 2) & 7) << 2;
    const int r1l = (tid * 2 + 1) >> 3,  c1l = ((tid * 2 + 1) & 7) << 2;
    const float* WB0 = &W[(size_t)(((r0l >> 4) << 10) + hb + (r0l & 15)) * Hsz];
    const float* WB1 = &W[(size_t)(((r1l >> 4) << 10) + hb + (r1l & 15)) * Hsz];

    float acc[2][2][4];
#pragma unroll
    for (int mf = 0; mf < 2; mf++)
#pragma unroll
        for (int nf = 0; nf < 2; nf++)
#pragma unroll
            for (int i = 0; i < 4; i++) acc[mf][nf][i] = 0.f;

#define P2_LOAD(st, k0)                                                          \
    {                                                                            \
        cp16(&ASF(sbuf, st, r0l, c0l), &hprev[r0l * Hsz + (k0) + c0l]);          \
        cp16(&BSF(sbuf, st, r0l, c0l), &WB0[(k0) + c0l]);                        \
        cp16(&ASF(sbuf, st, r1l, c1l), &hprev[r1l * Hsz + (k0) + c1l]);          \
        cp16(&BSF(sbuf, st, r1l, c1l), &WB1[(k0) + c1l]);                        \
        CP_COMMIT();                                                             \
    }

    P2_LOAD(0, 0)
    const int NIT = Hsz / 32;   // 32
    for (int it = 0; it < NIT; it++) {
        CP_WAIT0();
        __syncthreads();
        if (it + 1 < NIT) P2_LOAD((it + 1) & 1, (it + 1) * 32)
        TILE_COMPUTE(sbuf, it & 1)
        __syncthreads();
    }

    // Gate tile overlays stage memory (all reads of sbuf are done)
    __syncthreads();
    float* Gt = sbuf;   // [64][65]
#pragma unroll
    for (int mf = 0; mf < 2; mf++) {
        int r0 = warp_m * 32 + mf * 16 + groupID;
#pragma unroll
        for (int nf = 0; nf < 2; nf++) {
            int c0 = warp_n * 16 + nf * 8 + 2 * tig;
            Gt[r0 * 65 + c0]           = acc[mf][nf][0];
            Gt[r0 * 65 + c0 + 1]       = acc[mf][nf][1];
            Gt[(r0 + 8) * 65 + c0]     = acc[mf][nf][2];
            Gt[(r0 + 8) * 65 + c0 + 1] = acc[mf][nf][3];
        }
    }
    __syncthreads();

    const int t_in = dir ? (Tlen - 1 - s) : s;
    float* __restrict__ hnew = g_h[par ^ 1][dir];
    float* __restrict__ cst  = g_c[dir];

    for (int i = tid; i < Bsz * 16; i += 256) {
        int b = i >> 4;
        int j = i & 15;
        int h = hb + j;
        const float* gx = &g_G[((size_t)b * Tlen + t_in) * NTOT + dir * G4H];
        float gi = Gt[b * 65 + j]      + gx[h];
        float gf = Gt[b * 65 + 16 + j] + gx[Hsz + h];
        float gg = Gt[b * 65 + 32 + j] + gx[2 * Hsz + h];
        float go = Gt[b * 65 + 48 + j] + gx[3 * Hsz + h];

        float si = 1.f / (1.f + expf(-gi));
        float sf = 1.f / (1.f + expf(-gf));
        float so = 1.f / (1.f + expf(-go));
        float tg = tanhf(gg);

        int ci = b * Hsz + h;
        float cn = sf * cst[ci] + si * tg;
        cst[ci] = cn;
        float hn = so * tanhf(cn);
        hnew[ci] = hn;
        out[((size_t)b * Tlen + s) * (2 * Hsz) + dir * Hsz + h] = hn;
    }
}

// ---------------------------------------------------------------------------
// Phase 3: decoder-init projections (fp32, tiny)
// ---------------------------------------------------------------------------
__global__ __launch_bounds__(128) void proj_kernel(
    const float* __restrict__ fhW, const float* __restrict__ fhb,
    const float* __restrict__ fcW, const float* __restrict__ fcb,
    float* __restrict__ out2)
{
    __shared__ float As[64][17];
    __shared__ float Bs[64][17];

    const int which = blockIdx.y;
    const float* __restrict__ W    = which ? fcW : fhW;
    const float* __restrict__ bias = which ? fcb : fhb;
    const float* __restrict__ src0 = which ? g_c[0] : g_h[0][0];
    const float* __restrict__ src1 = which ? g_c[1] : g_h[0][1];

    const int d0  = blockIdx.x * 64;
    const int tid = threadIdx.x;
    const int ty  = tid >> 4;
    const int tx  = tid & 15;

    float acc[8][4];
#pragma unroll
    for (int r = 0; r < 8; r++)
#pragma unroll
        for (int c = 0; c < 4; c++) acc[r][c] = 0.f;

    for (int k0 = 0; k0 < 2 * Hsz; k0 += 16) {
#pragma unroll
        for (int i = 0; i < 2; i++) {
            int idx = tid * 2 + i;
            int row = idx >> 2;
            int c4  = (idx & 3) << 2;
            int k   = k0 + c4;
            const float* sp = (k < Hsz) ? &src0[row * Hsz + k]
                                        : &src1[row * Hsz + k - Hsz];
            float4 v = *(const float4*)sp;
            As[row][c4 + 0] = v.x; As[row][c4 + 1] = v.y;
            As[row][c4 + 2] = v.z; As[row][c4 + 3] = v.w;

            float4 w = *(const float4*)&W[(size_t)(d0 + row) * (2 * Hsz) + k0 + c4];
            Bs[row][c4 + 0] = w.x; Bs[row][c4 + 1] = w.y;
            Bs[row][c4 + 2] = w.z; Bs[row][c4 + 3] = w.w;
        }
        __syncthreads();
#pragma unroll
        for (int kk = 0; kk < 16; kk++) {
            float a[8], b[4];
#pragma unroll
            for (int r = 0; r < 8; r++) a[r] = As[ty * 8 + r][kk];
#pragma unroll
            for (int c = 0; c < 4; c++) b[c] = Bs[tx + 16 * c][kk];
#pragma unroll
            for (int r = 0; r < 8; r++)
#pragma unroll
                for (int c = 0; c < 4; c++) acc[r][c] += a[r] * b[c];
        }
        __syncthreads();
    }

#pragma unroll
    for (int c = 0; c < 4; c++) {
        int d = d0 + tx + 16 * c;
        float bv = bias[d];
#pragma unroll
        for (int r = 0; r < 8; r++) {
            int b = ty * 8 + r;
            out2[(size_t)which * (Bsz * Hsz) + b * Hsz + d] = tanhf(acc[r][c] + bv);
        }
    }
}

// ---------------------------------------------------------------------------
// Launch
// ---------------------------------------------------------------------------
extern "C" void kernel_launch(void* const* d_in, const int* in_sizes, int n_in,
                              void* d_out, int out_size)
{
    const float* X    = (const float*)d_in[0];
    const float* Wihf = (const float*)d_in[1];
    const float* Whhf = (const float*)d_in[2];
    const float* bihf = (const float*)d_in[3];
    const float* bhhf = (const float*)d_in[4];
    const float* Wihb = (const float*)d_in[5];
    const float* Whhb = (const float*)d_in[6];
    const float* bihb = (const float*)d_in[7];
    const float* bhhb = (const float*)d_in[8];
    const float* fcW  = (const float*)d_in[9];
    const float* fcb  = (const float*)d_in[10];
    const float* fhW  = (const float*)d_in[11];
    const float* fhb  = (const float*)d_in[12];
    float* out = (float*)d_out;

    zero_state_kernel<<<(Bsz * Hsz + 255) / 256, 256>>>();

    gemm_x_mma<<<dim3(NTOT / 64, MROWS / 64), 256>>>(
        X, Wihf, Wihb, bihf, bhhf, bihb, bhhb);

    for (int s = 0; s < Tlen; s++) {
        lstm_step_mma<<<128, 256>>>(Whhf, Whhb, out, s, s & 1);
    }

    proj_kernel<<<dim3(Hsz / 64, 2), 128>>>(
        fhW, fhb, fcW, fcb, out + (size_t)Bsz * Tlen * 2 * Hsz);
}

// round 4
// speedup vs baseline: 3.0307x; 1.1063x over previous
#include <cuda_runtime.h>
#include <cstdint>
#include <cstddef>

#define Bsz   64
#define Tlen  512
#define DIN   512
#define Hsz   1024
#define G4H   4096
#define NTOT  8192
#define MROWS 32768

// ---------------------------------------------------------------------------
// Persistent scratch
// ---------------------------------------------------------------------------
__device__ float    g_G[(size_t)MROWS * NTOT];       // gate preactivations (x-part + bias)
__device__ float    g_h[2][2][Bsz * Hsz];            // [parity][dir] fp32 (for proj)
__device__ float    g_c[2][Bsz * Hsz];               // [dir]
__device__ uint32_t g_h_t[2][2][Bsz * Hsz];          // tf32 copy of h
__device__ uint32_t g_X_t[(size_t)MROWS * DIN];      // tf32 X
__device__ uint32_t g_Wih_t[(size_t)NTOT * DIN];     // tf32 [Wih_f ; Wih_b]
__device__ uint32_t g_Whh_t[2][(size_t)G4H * Hsz];   // tf32 W_hh per dir

__global__ void zero_state_kernel() {
    int i = blockIdx.x * blockDim.x + threadIdx.x;
    if (i < Bsz * Hsz) {
        g_h[0][0][i] = 0.f;  g_h[0][1][i] = 0.f;
        g_c[0][i] = 0.f;     g_c[1][i] = 0.f;
        g_h_t[0][0][i] = 0u; g_h_t[0][1][i] = 0u;
    }
}

// ---------------------------------------------------------------------------
// Helpers
// ---------------------------------------------------------------------------
__device__ __forceinline__ uint32_t f2tf32(float x) {
    uint32_t r;
    asm("cvt.rna.tf32.f32 %0, %1;" : "=r"(r) : "f"(x));
    return r;
}
__device__ __forceinline__ void mma_tf32(float* c, const uint32_t* a, const uint32_t* b) {
    asm volatile(
        "mma.sync.aligned.m16n8k8.row.col.f32.tf32.tf32.f32 "
        "{%0,%1,%2,%3},{%4,%5,%6,%7},{%8,%9},{%0,%1,%2,%3};"
        : "+f"(c[0]), "+f"(c[1]), "+f"(c[2]), "+f"(c[3])
        : "r"(a[0]), "r"(a[1]), "r"(a[2]), "r"(a[3]), "r"(b[0]), "r"(b[1]));
}
__device__ __forceinline__ void cp16u(uint32_t* smem, const uint32_t* g) {
    uint32_t sa = (uint32_t)__cvta_generic_to_shared(smem);
    asm volatile("cp.async.ca.shared.global [%0], [%1], 16;" :: "r"(sa), "l"(g));
}
#define CP_COMMIT() asm volatile("cp.async.commit_group;")
#define CP_WAIT2()  asm volatile("cp.async.wait_group 2;")

// ---------------------------------------------------------------------------
// One-time tf32 conversion of X, Wih (concat), Whh
// ---------------------------------------------------------------------------
#define NX    ((size_t)MROWS * DIN)          // 16,777,216
#define NWIH1 ((size_t)G4H * DIN)            //  2,097,152
#define NWHH1 ((size_t)G4H * Hsz)            //  4,194,304
__global__ __launch_bounds__(256) void convert_kernel(
    const float* __restrict__ X,
    const float* __restrict__ Wihf, const float* __restrict__ Wihb,
    const float* __restrict__ Whhf, const float* __restrict__ Whhb)
{
    size_t base = ((size_t)blockIdx.x * 256 + threadIdx.x) * 4;
    const float* src;
    uint32_t* dst;
    if (base < NX)                      { src = X    + base;                dst = g_X_t   + base; }
    else if (base < NX + NWIH1)         { size_t o = base - NX;             src = Wihf + o; dst = g_Wih_t + o; }
    else if (base < NX + 2 * NWIH1)     { size_t o = base - NX - NWIH1;     src = Wihb + o; dst = g_Wih_t + NWIH1 + o; }
    else if (base < NX + 2*NWIH1 + NWHH1) { size_t o = base - NX - 2*NWIH1; src = Whhf + o; dst = g_Whh_t[0] + o; }
    else                                { size_t o = base - NX - 2*NWIH1 - NWHH1; src = Whhb + o; dst = g_Whh_t[1] + o; }
    float4 v = *(const float4*)src;
    uint4 u;
    u.x = f2tf32(v.x); u.y = f2tf32(v.y); u.z = f2tf32(v.z); u.w = f2tf32(v.w);
    *(uint4*)dst = u;
}

// ---------------------------------------------------------------------------
// Shared GEMM tile machinery: 64x64 tile, BK=16, 4-stage cp.async ring
// smem: 4 A stages + 4 B stages, row stride 20 u32 -> 40,960 B total
// ---------------------------------------------------------------------------
#define SST 20
#define STG (64 * SST)
#define ASU(st, r, c) sbuf[(st) * STG + (r) * SST + (c)]
#define BSU(st, r, c) sbuf[4 * STG + (st) * STG + (r) * SST + (c)]

#define TILE_COMPUTE16(st)                                                       \
    _Pragma("unroll")                                                            \
    for (int kk = 0; kk < 16; kk += 8) {                                         \
        uint32_t a_[2][4], b_[2][2];                                             \
        _Pragma("unroll")                                                        \
        for (int mf = 0; mf < 2; mf++) {                                         \
            int r = warp_m * 32 + mf * 16 + groupID;                             \
            a_[mf][0] = ASU(st, r,     kk + tig);                                \
            a_[mf][1] = ASU(st, r + 8, kk + tig);                                \
            a_[mf][2] = ASU(st, r,     kk + tig + 4);                            \
            a_[mf][3] = ASU(st, r + 8, kk + tig + 4);                            \
        }                                                                        \
        _Pragma("unroll")                                                        \
        for (int nf = 0; nf < 2; nf++) {                                         \
            int n = warp_n * 16 + nf * 8 + groupID;                              \
            b_[nf][0] = BSU(st, n, kk + tig);                                    \
            b_[nf][1] = BSU(st, n, kk + tig + 4);                                \
        }                                                                        \
        _Pragma("unroll")                                                        \
        for (int mf = 0; mf < 2; mf++)                                           \
            _Pragma("unroll")                                                    \
            for (int nf = 0; nf < 2; nf++)                                       \
                mma_tf32(acc[mf][nf], a_[mf], b_[nf]);                           \
    }

// ---------------------------------------------------------------------------
// Phase 1: G = X @ [Wf|Wb]^T + bias  (M=32768, N=8192, K=512)
// ---------------------------------------------------------------------------
__global__ __launch_bounds__(256) void gemm_x_mma(
    const float* __restrict__ bihf, const float* __restrict__ bhhf,
    const float* __restrict__ bihb, const float* __restrict__ bhhb)
{
    __shared__ uint32_t sbuf[8 * STG];

    const int n0  = blockIdx.x * 64;
    const int m0  = blockIdx.y * 64;
    const int tid = threadIdx.x;
    const int wid = tid >> 5, lane = tid & 31;
    const int warp_m = wid & 1, warp_n = wid >> 1;
    const int groupID = lane >> 2, tig = lane & 3;

    // per-thread load coords: one 16B per matrix per stage
    const int r_l = tid >> 2, c_l = (tid & 3) << 2;
    const uint32_t* At = g_X_t   + (size_t)(m0 + r_l) * DIN;
    const uint32_t* Bt = g_Wih_t + (size_t)(n0 + r_l) * DIN;

    float acc[2][2][4];
#pragma unroll
    for (int mf = 0; mf < 2; mf++)
#pragma unroll
        for (int nf = 0; nf < 2; nf++)
#pragma unroll
            for (int i = 0; i < 4; i++) acc[mf][nf][i] = 0.f;

#define P1_LOAD(st, k0)                                        \
    { cp16u(&ASU(st, r_l, c_l), At + (k0) + c_l);              \
      cp16u(&BSU(st, r_l, c_l), Bt + (k0) + c_l);              \
      CP_COMMIT(); }

    P1_LOAD(0, 0) P1_LOAD(1, 16) P1_LOAD(2, 32)
    const int NIT = DIN / 16;   // 32
    for (int it = 0; it < NIT; it++) {
        CP_WAIT2();
        __syncthreads();
        if (it + 3 < NIT) P1_LOAD((it + 3) & 3, (it + 3) * 16)
        else              CP_COMMIT();
        TILE_COMPUTE16(it & 3)
    }

#pragma unroll
    for (int nf = 0; nf < 2; nf++) {
        int c0 = warp_n * 16 + nf * 8 + 2 * tig;
        int n  = n0 + c0;
        float bias0, bias1;
        if (n < G4H) { bias0 = bihf[n] + bhhf[n]; bias1 = bihf[n + 1] + bhhf[n + 1]; }
        else         { bias0 = bihb[n - G4H] + bhhb[n - G4H];
                       bias1 = bihb[n + 1 - G4H] + bhhb[n + 1 - G4H]; }
#pragma unroll
        for (int mf = 0; mf < 2; mf++) {
            int r0 = m0 + warp_m * 32 + mf * 16 + groupID;
            float2 v0 = make_float2(acc[mf][nf][0] + bias0, acc[mf][nf][1] + bias1);
            float2 v1 = make_float2(acc[mf][nf][2] + bias0, acc[mf][nf][3] + bias1);
            *(float2*)&g_G[(size_t)r0 * NTOT + n]       = v0;
            *(float2*)&g_G[(size_t)(r0 + 8) * NTOT + n] = v1;
        }
    }
}

// ---------------------------------------------------------------------------
// Phase 2: one LSTM timestep (both dirs). grid=128: dir=bx>>6, hb=(bx&63)*16.
// Tile M=64 (batch) x N=64 (4 gates x 16 h), K=1024, 4-stage pipeline.
// ---------------------------------------------------------------------------
__global__ __launch_bounds__(256) void lstm_step_mma(
    float* __restrict__ out, int s, int par)
{
    __shared__ uint32_t sbuf[8 * STG];

    const int dir = blockIdx.x >> 6;
    const int hb  = (blockIdx.x & 63) << 4;
    const int tid = threadIdx.x;
    const int wid = tid >> 5, lane = tid & 31;
    const int warp_m = wid & 1, warp_n = wid >> 1;
    const int groupID = lane >> 2, tig = lane & 3;
    const int t_in = dir ? (Tlen - 1 - s) : s;

    const int r_l = tid >> 2, c_l = (tid & 3) << 2;
    const uint32_t* At = g_h_t[par][dir] + (size_t)r_l * Hsz;
    const uint32_t* Wt = g_Whh_t[dir] +
        (size_t)(((r_l >> 4) << 10) + hb + (r_l & 15)) * Hsz;

    // Prefetch gate-x preactivations + c state (land during the GEMM)
    float gx4[4][4], cv[4];
#pragma unroll
    for (int q = 0; q < 4; q++) {
        int i = tid + q * 256;
        int b = i >> 4, j = i & 15, h = hb + j;
        const float* gx = g_G + ((size_t)b * Tlen + t_in) * NTOT + dir * G4H + h;
        gx4[q][0] = __ldg(gx);
        gx4[q][1] = __ldg(gx + Hsz);
        gx4[q][2] = __ldg(gx + 2 * Hsz);
        gx4[q][3] = __ldg(gx + 3 * Hsz);
        cv[q]     = __ldg(&g_c[dir][b * Hsz + h]);
    }

    float acc[2][2][4];
#pragma unroll
    for (int mf = 0; mf < 2; mf++)
#pragma unroll
        for (int nf = 0; nf < 2; nf++)
#pragma unroll
            for (int i = 0; i < 4; i++) acc[mf][nf][i] = 0.f;

#define P2_LOAD(st, k0)                                        \
    { cp16u(&ASU(st, r_l, c_l), At + (k0) + c_l);              \
      cp16u(&BSU(st, r_l, c_l), Wt + (k0) + c_l);              \
      CP_COMMIT(); }

    P2_LOAD(0, 0) P2_LOAD(1, 16) P2_LOAD(2, 32)
    const int NIT = Hsz / 16;   // 64
    for (int it = 0; it < NIT; it++) {
        CP_WAIT2();
        __syncthreads();
        if (it + 3 < NIT) P2_LOAD((it + 3) & 3, (it + 3) * 16)
        else              CP_COMMIT();
        TILE_COMPUTE16(it & 3)
    }

    // Gate tile overlays stage memory
    __syncthreads();
    float* Gt = (float*)sbuf;   // [64][65]
#pragma unroll
    for (int mf = 0; mf < 2; mf++) {
        int r0 = warp_m * 32 + mf * 16 + groupID;
#pragma unroll
        for (int nf = 0; nf < 2; nf++) {
            int c0 = warp_n * 16 + nf * 8 + 2 * tig;
            Gt[r0 * 65 + c0]           = acc[mf][nf][0];
            Gt[r0 * 65 + c0 + 1]       = acc[mf][nf][1];
            Gt[(r0 + 8) * 65 + c0]     = acc[mf][nf][2];
            Gt[(r0 + 8) * 65 + c0 + 1] = acc[mf][nf][3];
        }
    }
    __syncthreads();

    float*    __restrict__ hnew  = g_h[par ^ 1][dir];
    uint32_t* __restrict__ hnewt = g_h_t[par ^ 1][dir];
    float*    __restrict__ cst   = g_c[dir];

#pragma unroll
    for (int q = 0; q < 4; q++) {
        int i = tid + q * 256;
        int b = i >> 4, j = i & 15, h = hb + j;
        float gi = Gt[b * 65 + j]      + gx4[q][0];
        float gf = Gt[b * 65 + 16 + j] + gx4[q][1];
        float gg = Gt[b * 65 + 32 + j] + gx4[q][2];
        float go = Gt[b * 65 + 48 + j] + gx4[q][3];

        float si = 1.f / (1.f + expf(-gi));
        float sf = 1.f / (1.f + expf(-gf));
        float so = 1.f / (1.f + expf(-go));
        float tg = tanhf(gg);

        float cn = sf * cv[q] + si * tg;
        cst[b * Hsz + h] = cn;
        float hn = so * tanhf(cn);
        hnew[b * Hsz + h]  = hn;
        hnewt[b * Hsz + h] = f2tf32(hn);
        out[((size_t)b * Tlen + s) * (2 * Hsz) + dir * Hsz + h] = hn;
    }
}

// ---------------------------------------------------------------------------
// Phase 3: decoder-init projections (fp32, tiny)
// ---------------------------------------------------------------------------
__global__ __launch_bounds__(128) void proj_kernel(
    const float* __restrict__ fhW, const float* __restrict__ fhb,
    const float* __restrict__ fcW, const float* __restrict__ fcb,
    float* __restrict__ out2)
{
    __shared__ float As[64][17];
    __shared__ float Bs[64][17];

    const int which = blockIdx.y;
    const float* __restrict__ W    = which ? fcW : fhW;
    const float* __restrict__ bias = which ? fcb : fhb;
    const float* __restrict__ src0 = which ? g_c[0] : g_h[0][0];
    const float* __restrict__ src1 = which ? g_c[1] : g_h[0][1];

    const int d0  = blockIdx.x * 64;
    const int tid = threadIdx.x;
    const int ty  = tid >> 4;
    const int tx  = tid & 15;

    float acc[8][4];
#pragma unroll
    for (int r = 0; r < 8; r++)
#pragma unroll
        for (int c = 0; c < 4; c++) acc[r][c] = 0.f;

    for (int k0 = 0; k0 < 2 * Hsz; k0 += 16) {
#pragma unroll
        for (int i = 0; i < 2; i++) {
            int idx = tid * 2 + i;
            int row = idx >> 2;
            int c4  = (idx & 3) << 2;
            int k   = k0 + c4;
            const float* sp = (k < Hsz) ? &src0[row * Hsz + k]
                                        : &src1[row * Hsz + k - Hsz];
            float4 v = *(const float4*)sp;
            As[row][c4 + 0] = v.x; As[row][c4 + 1] = v.y;
            As[row][c4 + 2] = v.z; As[row][c4 + 3] = v.w;

            float4 w = *(const float4*)&W[(size_t)(d0 + row) * (2 * Hsz) + k0 + c4];
            Bs[row][c4 + 0] = w.x; Bs[row][c4 + 1] = w.y;
            Bs[row][c4 + 2] = w.z; Bs[row][c4 + 3] = w.w;
        }
        __syncthreads();
#pragma unroll
        for (int kk = 0; kk < 16; kk++) {
            float a[8], b[4];
#pragma unroll
            for (int r = 0; r < 8; r++) a[r] = As[ty * 8 + r][kk];
#pragma unroll
            for (int c = 0; c < 4; c++) b[c] = Bs[tx + 16 * c][kk];
#pragma unroll
            for (int r = 0; r < 8; r++)
#pragma unroll
                for (int c = 0; c < 4; c++) acc[r][c] += a[r] * b[c];
        }
        __syncthreads();
    }

#pragma unroll
    for (int c = 0; c < 4; c++) {
        int d = d0 + tx + 16 * c;
        float bv = bias[d];
#pragma unroll
        for (int r = 0; r < 8; r++) {
            int b = ty * 8 + r;
            out2[(size_t)which * (Bsz * Hsz) + b * Hsz + d] = tanhf(acc[r][c] + bv);
        }
    }
}

// ---------------------------------------------------------------------------
// Launch
// ---------------------------------------------------------------------------
extern "C" void kernel_launch(void* const* d_in, const int* in_sizes, int n_in,
                              void* d_out, int out_size)
{
    const float* X    = (const float*)d_in[0];
    const float* Wihf = (const float*)d_in[1];
    const float* Whhf = (const float*)d_in[2];
    const float* bihf = (const float*)d_in[3];
    const float* bhhf = (const float*)d_in[4];
    const float* Wihb = (const float*)d_in[5];
    const float* Whhb = (const float*)d_in[6];
    const float* bihb = (const float*)d_in[7];
    const float* bhhb = (const float*)d_in[8];
    const float* fcW  = (const float*)d_in[9];
    const float* fcb  = (const float*)d_in[10];
    const float* fhW  = (const float*)d_in[11];
    const float* fhb  = (const float*)d_in[12];
    float* out = (float*)d_out;

    zero_state_kernel<<<(Bsz * Hsz + 255) / 256, 256>>>();

    // One-time tf32 conversion (29.36M elements, 4 per thread)
    convert_kernel<<<(unsigned)((NX + 2 * NWIH1 + 2 * NWHH1) / 4 / 256), 256>>>(
        X, Wihf, Wihb, Whhf, Whhb);

    gemm_x_mma<<<dim3(NTOT / 64, MROWS / 64), 256>>>(bihf, bhhf, bihb, bhhb);

    for (int s = 0; s < Tlen; s++) {
        lstm_step_mma<<<128, 256>>>(out, s, s & 1);
    }

    proj_kernel<<<dim3(Hsz / 64, 2), 128>>>(
        fhW, fhb, fcW, fcb, out + (size_t)Bsz * Tlen * 2 * Hsz);
}

// round 6
// speedup vs baseline: 6.2203x; 2.0524x over previous
#include <cuda_runtime.h>
#include <cuda_fp16.h>
#include <cstdint>
#include <cstddef>

#define Bsz   64
#define Tlen  512
#define DIN   512
#define Hsz   1024
#define G4H   4096
#define NTOT  8192
#define MROWS 32768

// ---------------------------------------------------------------------------
// Persistent scratch
// ---------------------------------------------------------------------------
__device__ float    g_G[(size_t)MROWS * NTOT];     // gate preactivations (x-part + bias)
__device__ __half   g_h_half[2][2][Bsz * Hsz];     // [parity][dir] h in fp16
__device__ float    g_hT[2][Bsz * Hsz];            // final h (for proj)
__device__ float    g_cT[2][Bsz * Hsz];            // final c (for proj)
__device__ __half   g_X_h[(size_t)MROWS * DIN];
__device__ __half   g_Wih_h[(size_t)NTOT * DIN];   // [Wih_f ; Wih_b]
__device__ __half   g_Whh_h[2][(size_t)G4H * Hsz];
__device__ unsigned g_flags[128 * 32];             // grid barrier flags (128B apart)

__global__ void zero_state_kernel() {
    int i = blockIdx.x * blockDim.x + threadIdx.x;
    if (i < Bsz * Hsz) {
        g_h_half[0][0][i] = __float2half(0.f);
        g_h_half[0][1][i] = __float2half(0.f);
    }
    if (i < 128 * 32) g_flags[i] = 0u;
}

// ---------------------------------------------------------------------------
// Helpers
// ---------------------------------------------------------------------------
__device__ __forceinline__ void mma_f16(float* c, const uint32_t* a, const uint32_t* b) {
    asm volatile(
        "mma.sync.aligned.m16n8k16.row.col.f32.f16.f16.f32 "
        "{%0,%1,%2,%3},{%4,%5,%6,%7},{%8,%9},{%0,%1,%2,%3};"
        : "+f"(c[0]), "+f"(c[1]), "+f"(c[2]), "+f"(c[3])
        : "r"(a[0]), "r"(a[1]), "r"(a[2]), "r"(a[3]), "r"(b[0]), "r"(b[1]));
}
__device__ __forceinline__ void cp16(void* smem, const void* g) {
    uint32_t sa = (uint32_t)__cvta_generic_to_shared(smem);
    asm volatile("cp.async.ca.shared.global [%0], [%1], 16;" :: "r"(sa), "l"(g));
}
#define CP_COMMIT() asm volatile("cp.async.commit_group;")
#define CP_WAIT2()  asm volatile("cp.async.wait_group 2;")
#define CP_WAIT0()  asm volatile("cp.async.wait_group 0;")

// ---------------------------------------------------------------------------
// One-time fp16 conversion of X, Wih (concat), Whh  (8 elems/thread)
// ---------------------------------------------------------------------------
#define NX    ((size_t)MROWS * DIN)
#define NWIH1 ((size_t)G4H * DIN)
#define NWHH1 ((size_t)G4H * Hsz)
#define NCVT  (NX + 2 * NWIH1 + 2 * NWHH1)
__global__ __launch_bounds__(256) void convert_kernel(
    const float* __restrict__ X,
    const float* __restrict__ Wihf, const float* __restrict__ Wihb,
    const float* __restrict__ Whhf, const float* __restrict__ Whhb)
{
    size_t base = ((size_t)blockIdx.x * 256 + threadIdx.x) * 8;
    const float* src;
    __half* dst;
    if (base < NX)                        { src = X + base;                        dst = g_X_h + base; }
    else if (base < NX + NWIH1)           { size_t o = base - NX;                  src = Wihf + o; dst = g_Wih_h + o; }
    else if (base < NX + 2 * NWIH1)       { size_t o = base - NX - NWIH1;          src = Wihb + o; dst = g_Wih_h + NWIH1 + o; }
    else if (base < NX + 2*NWIH1 + NWHH1) { size_t o = base - NX - 2*NWIH1;        src = Whhf + o; dst = g_Whh_h[0] + o; }
    else                                  { size_t o = base - NX - 2*NWIH1 - NWHH1; src = Whhb + o; dst = g_Whh_h[1] + o; }
    float4 v0 = ((const float4*)src)[0];
    float4 v1 = ((const float4*)src)[1];
    __half2 h0 = __floats2half2_rn(v0.x, v0.y);
    __half2 h1 = __floats2half2_rn(v0.z, v0.w);
    __half2 h2 = __floats2half2_rn(v1.x, v1.y);
    __half2 h3 = __floats2half2_rn(v1.z, v1.w);
    uint4 u;
    u.x = *(uint32_t*)&h0; u.y = *(uint32_t*)&h1;
    u.z = *(uint32_t*)&h2; u.w = *(uint32_t*)&h3;
    *(uint4*)dst = u;
}

// ---------------------------------------------------------------------------
// Phase 1: G = X @ [Wf|Wb]^T + bias  (M=32768, N=8192, K=512), fp16 k16 MMA
// 64x64 tile, BK=32, 4-stage cp.async, 256 threads (8 warps, 32x16 warp tile)
// ---------------------------------------------------------------------------
#define P1ST 40                 // halfs per smem row (32 + 8 pad)
#define P1SZ (64 * P1ST)        // halfs per stage per matrix

__global__ __launch_bounds__(256) void gemm_x_mma(
    const float* __restrict__ bihf, const float* __restrict__ bhhf,
    const float* __restrict__ bihb, const float* __restrict__ bhhb)
{
    __shared__ __half asb[4][P1SZ];
    __shared__ __half bsb[4][P1SZ];

    const int n0  = blockIdx.x * 64;
    const int m0  = blockIdx.y * 64;
    const int tid = threadIdx.x;
    const int wid = tid >> 5, lane = tid & 31;
    const int warp_m = wid & 1, warp_n = wid >> 1;
    const int groupID = lane >> 2, tig = lane & 3;

    const int r_l = tid >> 2, u_l = (tid & 3) << 3;   // row, half-offset (16B)
    const __half* At = g_X_h   + (size_t)(m0 + r_l) * DIN;
    const __half* Bt = g_Wih_h + (size_t)(n0 + r_l) * DIN;

    float acc[2][2][4];
#pragma unroll
    for (int mf = 0; mf < 2; mf++)
#pragma unroll
        for (int nf = 0; nf < 2; nf++)
#pragma unroll
            for (int i = 0; i < 4; i++) acc[mf][nf][i] = 0.f;

#define P1_LOAD(st, k0)                                      \
    { cp16(&asb[st][r_l * P1ST + u_l], At + (k0) + u_l);     \
      cp16(&bsb[st][r_l * P1ST + u_l], Bt + (k0) + u_l);     \
      CP_COMMIT(); }

    P1_LOAD(0, 0) P1_LOAD(1, 32) P1_LOAD(2, 64)
    const int NIT = DIN / 32;   // 16
    for (int it = 0; it < NIT; it++) {
        CP_WAIT2();
        __syncthreads();
        if (it + 3 < NIT) P1_LOAD((it + 3) & 3, (it + 3) * 32)
        else              CP_COMMIT();
        const __half* A = asb[it & 3];
        const __half* B = bsb[it & 3];
#pragma unroll
        for (int ks = 0; ks < 2; ks++) {
            const int kk = ks * 16;
            uint32_t av[2][4], bv[2][2];
#pragma unroll
            for (int mf = 0; mf < 2; mf++) {
                int row = warp_m * 32 + mf * 16 + groupID;
                const uint32_t* ap = (const uint32_t*)(A + row * P1ST + kk + 2 * tig);
                av[mf][0] = ap[0];
                av[mf][2] = ap[4];
                const uint32_t* ap2 = (const uint32_t*)(A + (row + 8) * P1ST + kk + 2 * tig);
                av[mf][1] = ap2[0];
                av[mf][3] = ap2[4];
            }
#pragma unroll
            for (int nf = 0; nf < 2; nf++) {
                int n = warp_n * 16 + nf * 8 + groupID;
                const uint32_t* bp = (const uint32_t*)(B + n * P1ST + kk + 2 * tig);
                bv[nf][0] = bp[0];
                bv[nf][1] = bp[4];
            }
#pragma unroll
            for (int mf = 0; mf < 2; mf++)
#pragma unroll
                for (int nf = 0; nf < 2; nf++)
                    mma_f16(acc[mf][nf], av[mf], bv[nf]);
        }
        __syncthreads();
    }

#pragma unroll
    for (int nf = 0; nf < 2; nf++) {
        int c0 = warp_n * 16 + nf * 8 + 2 * tig;
        int n  = n0 + c0;
        float bias0, bias1;
        if (n < G4H) { bias0 = bihf[n] + bhhf[n]; bias1 = bihf[n + 1] + bhhf[n + 1]; }
        else         { bias0 = bihb[n - G4H] + bhhb[n - G4H];
                       bias1 = bihb[n + 1 - G4H] + bhhb[n + 1 - G4H]; }
#pragma unroll
        for (int mf = 0; mf < 2; mf++) {
            int r0 = m0 + warp_m * 32 + mf * 16 + groupID;
            float2 v0 = make_float2(acc[mf][nf][0] + bias0, acc[mf][nf][1] + bias1);
            float2 v1 = make_float2(acc[mf][nf][2] + bias0, acc[mf][nf][3] + bias1);
            *(float2*)&g_G[(size_t)r0 * NTOT + n]       = v0;
            *(float2*)&g_G[(size_t)(r0 + 8) * NTOT + n] = v1;
        }
    }
}

// ---------------------------------------------------------------------------
// Phase 2: PERSISTENT LSTM kernel. 128 CTAs (1/SM), all 512 steps in one
// launch, grid barrier between steps. dir = bid>>6, hb = (bid&63)*16.
// Per step: gates[64 b x 64 (4g x 16h)] = h @ Wslice^T; W slice (64x1024 fp16)
// resident in smem for the whole kernel. c lives in registers.
// ---------------------------------------------------------------------------
#define WST   1032                       // halfs per W smem row (1024 + 8 pad)
#define WBYTES (64 * WST * 2)            // 132,096
#define HST   40                         // halfs per h-stage row
#define HSSZ  (64 * HST)                 // halfs per h stage (2560)
#define DYNSZ (WBYTES + 4 * HSSZ * 2)    // + 20,480 = 153,  -> 152,576 B

__global__ __launch_bounds__(256, 1) void lstm_persist(float* __restrict__ out)
{
    extern __shared__ char smraw[];
    __half* ws = (__half*)smraw;                    // [64][WST]
    __half* hs = (__half*)(smraw + WBYTES);         // [4][HSSZ]
    float*  Gt = (float*)(smraw + WBYTES);          // overlay [64][68]

    const int bid = blockIdx.x;
    const int dir = bid >> 6;
    const int hb  = (bid & 63) << 4;
    const int tid = threadIdx.x;
    const int wid = tid >> 5, lane = tid & 31;
    const int warp_m = wid & 1, warp_n = wid >> 1;
    const int groupID = lane >> 2, tig = lane & 3;

    // ---- Load W slice into smem (once) ----
    {
        int r = tid >> 2, u = (tid & 3) << 3;
        int wrow = ((r >> 4) << 10) + hb + (r & 15);   // gate*1024 + hb + j
        const __half* src = g_Whh_h[dir] + (size_t)wrow * Hsz;
#pragma unroll
        for (int i = 0; i < 32; i++)
            cp16(&ws[r * WST + u + i * 32], src + u + i * 32);
        CP_COMMIT();
    }
    CP_WAIT0();
    __syncthreads();

    const int r_l = tid >> 2, u_l = (tid & 3) << 3;

    // Per-thread epilogue elements: e = tid + q*256 -> b = e>>4, j = e&15
    float cv[4];
#pragma unroll
    for (int q = 0; q < 4; q++) cv[q] = 0.f;

    for (int s = 0; s < Tlen; s++) {
        const int par  = s & 1;
        const int t_in = dir ? (Tlen - 1 - s) : s;
        const __half* Ht = g_h_half[par][dir];

        // Prefetch gate-x preactivations (overlap with GEMM)
        float gx4[4][4];
#pragma unroll
        for (int q = 0; q < 4; q++) {
            int e = tid + q * 256;
            int b = e >> 4, j = e & 15, h = hb + j;
            const float* gx = g_G + ((size_t)b * Tlen + t_in) * NTOT + dir * G4H + h;
            gx4[q][0] = __ldg(gx);
            gx4[q][1] = __ldg(gx + Hsz);
            gx4[q][2] = __ldg(gx + 2 * Hsz);
            gx4[q][3] = __ldg(gx + 3 * Hsz);
        }

        float acc[2][2][4];
#pragma unroll
        for (int mf = 0; mf < 2; mf++)
#pragma unroll
            for (int nf = 0; nf < 2; nf++)
#pragma unroll
                for (int i = 0; i < 4; i++) acc[mf][nf][i] = 0.f;

#define H_LOAD(st, k0)                                                  \
        { cp16(&hs[(st) * HSSZ + r_l * HST + u_l], Ht + r_l * Hsz + (k0) + u_l); \
          CP_COMMIT(); }

        H_LOAD(0, 0) H_LOAD(1, 32) H_LOAD(2, 64)
        for (int it = 0; it < 32; it++) {
            CP_WAIT2();
            __syncthreads();
            if (it + 3 < 32) H_LOAD((it + 3) & 3, (it + 3) * 32)
            else             CP_COMMIT();
            const __half* A = hs + (it & 3) * HSSZ;
#pragma unroll
            for (int ks = 0; ks < 2; ks++) {
                const int kk = ks * 16;
                uint32_t av[2][4], bv[2][2];
#pragma unroll
                for (int mf = 0; mf < 2; mf++) {
                    int row = warp_m * 32 + mf * 16 + groupID;
                    const uint32_t* ap = (const uint32_t*)(A + row * HST + kk + 2 * tig);
                    av[mf][0] = ap[0];
                    av[mf][2] = ap[4];
                    const uint32_t* ap2 = (const uint32_t*)(A + (row + 8) * HST + kk + 2 * tig);
                    av[mf][1] = ap2[0];
                    av[mf][3] = ap2[4];
                }
#pragma unroll
                for (int nf = 0; nf < 2; nf++) {
                    int n = warp_n * 16 + nf * 8 + groupID;
                    const uint32_t* bp =
                        (const uint32_t*)(ws + n * WST + it * 32 + kk + 2 * tig);
                    bv[nf][0] = bp[0];
                    bv[nf][1] = bp[4];
                }
#pragma unroll
                for (int mf = 0; mf < 2; mf++)
#pragma unroll
                    for (int nf = 0; nf < 2; nf++)
                        mma_f16(acc[mf][nf], av[mf], bv[nf]);
            }
            __syncthreads();
        }

        // Scatter acc to Gt (overlays h stages: all stage reads are done)
#pragma unroll
        for (int mf = 0; mf < 2; mf++) {
            int r0 = warp_m * 32 + mf * 16 + groupID;
#pragma unroll
            for (int nf = 0; nf < 2; nf++) {
                int c0 = warp_n * 16 + nf * 8 + 2 * tig;
                Gt[r0 * 68 + c0]           = acc[mf][nf][0];
                Gt[r0 * 68 + c0 + 1]       = acc[mf][nf][1];
                Gt[(r0 + 8) * 68 + c0]     = acc[mf][nf][2];
                Gt[(r0 + 8) * 68 + c0 + 1] = acc[mf][nf][3];
            }
        }
        __syncthreads();

        // Cell update
        __half* hnewh = g_h_half[par ^ 1][dir];
#pragma unroll
        for (int q = 0; q < 4; q++) {
            int e = tid + q * 256;
            int b = e >> 4, j = e & 15, h = hb + j;
            float gi = Gt[b * 68 + j]      + gx4[q][0];
            float gf = Gt[b * 68 + 16 + j] + gx4[q][1];
            float gg = Gt[b * 68 + 32 + j] + gx4[q][2];
            float go = Gt[b * 68 + 48 + j] + gx4[q][3];

            float si = 1.f / (1.f + expf(-gi));
            float sf = 1.f / (1.f + expf(-gf));
            float so = 1.f / (1.f + expf(-go));
            float tg = tanhf(gg);

            float cn = sf * cv[q] + si * tg;
            cv[q] = cn;
            float hn = so * tanhf(cn);
            hnewh[b * Hsz + h] = __float2half_rn(hn);
            out[((size_t)b * Tlen + s) * (2 * Hsz) + dir * Hsz + h] = hn;
            if (s == Tlen - 1) {
                g_hT[dir][b * Hsz + h] = hn;
                g_cT[dir][b * Hsz + h] = cn;
            }
        }
        __syncthreads();

        // ---- Grid barrier ----
        if (tid == 0) {
            unsigned* fl = &g_flags[bid * 32];
            asm volatile("st.release.gpu.u32 [%0], %1;" :: "l"(fl), "r"((unsigned)(s + 1)) : "memory");
        }
        if (tid < 128) {
            unsigned* fl = &g_flags[tid * 32];
            unsigned v;
            do {
                asm volatile("ld.acquire.gpu.u32 %0, [%1];" : "=r"(v) : "l"(fl) : "memory");
                if (v < (unsigned)(s + 1)) __nanosleep(40);
            } while (v < (unsigned)(s + 1));
        }
        __syncthreads();
    }
}

// ---------------------------------------------------------------------------
// Phase 3: decoder-init projections (fp32, tiny)
// ---------------------------------------------------------------------------
__global__ __launch_bounds__(128) void proj_kernel(
    const float* __restrict__ fhW, const float* __restrict__ fhb,
    const float* __restrict__ fcW, const float* __restrict__ fcb,
    float* __restrict__ out2)
{
    __shared__ float As[64][17];
    __shared__ float Bs[64][17];

    const int which = blockIdx.y;
    const float* __restrict__ W    = which ? fcW : fhW;
    const float* __restrict__ bias = which ? fcb : fhb;
    const float* __restrict__ src0 = which ? g_cT[0] : g_hT[0];
    const float* __restrict__ src1 = which ? g_cT[1] : g_hT[1];

    const int d0  = blockIdx.x * 64;
    const int tid = threadIdx.x;
    const int ty  = tid >> 4;
    const int tx  = tid & 15;

    float acc[8][4];
#pragma unroll
    for (int r = 0; r < 8; r++)
#pragma unroll
        for (int c = 0; c < 4; c++) acc[r][c] = 0.f;

    for (int k0 = 0; k0 < 2 * Hsz; k0 += 16) {
#pragma unroll
        for (int i = 0; i < 2; i++) {
            int idx = tid * 2 + i;
            int row = idx >> 2;
            int c4  = (idx & 3) << 2;
            int k   = k0 + c4;
            const float* sp = (k < Hsz) ? &src0[row * Hsz + k]
                                        : &src1[row * Hsz + k - Hsz];
            float4 v = *(const float4*)sp;
            As[row][c4 + 0] = v.x; As[row][c4 + 1] = v.y;
            As[row][c4 + 2] = v.z; As[row][c4 + 3] = v.w;

            float4 w = *(const float4*)&W[(size_t)(d0 + row) * (2 * Hsz) + k0 + c4];
            Bs[row][c4 + 0] = w.x; Bs[row][c4 + 1] = w.y;
            Bs[row][c4 + 2] = w.z; Bs[row][c4 + 3] = w.w;
        }
        __syncthreads();
#pragma unroll
        for (int kk = 0; kk < 16; kk++) {
            float a[8], b[4];
#pragma unroll
            for (int r = 0; r < 8; r++) a[r] = As[ty * 8 + r][kk];
#pragma unroll
            for (int c = 0; c < 4; c++) b[c] = Bs[tx + 16 * c][kk];
#pragma unroll
            for (int r = 0; r < 8; r++)
#pragma unroll
                for (int c = 0; c < 4; c++) acc[r][c] += a[r] * b[c];
        }
        __syncthreads();
    }

#pragma unroll
    for (int c = 0; c < 4; c++) {
        int d = d0 + tx + 16 * c;
        float bv = bias[d];
#pragma unroll
        for (int r = 0; r < 8; r++) {
            int b = ty * 8 + r;
            out2[(size_t)which * (Bsz * Hsz) + b * Hsz + d] = tanhf(acc[r][c] + bv);
        }
    }
}

// ---------------------------------------------------------------------------
// Launch
// ---------------------------------------------------------------------------
extern "C" void kernel_launch(void* const* d_in, const int* in_sizes, int n_in,
                              void* d_out, int out_size)
{
    const float* X    = (const float*)d_in[0];
    const float* Wihf = (const float*)d_in[1];
    const float* Whhf = (const float*)d_in[2];
    const float* bihf = (const float*)d_in[3];
    const float* bhhf = (const float*)d_in[4];
    const float* Wihb = (const float*)d_in[5];
    const float* Whhb = (const float*)d_in[6];
    const float* bihb = (const float*)d_in[7];
    const float* bhhb = (const float*)d_in[8];
    const float* fcW  = (const float*)d_in[9];
    const float* fcb  = (const float*)d_in[10];
    const float* fhW  = (const float*)d_in[11];
    const float* fhb  = (const float*)d_in[12];
    float* out = (float*)d_out;

    cudaFuncSetAttribute(lstm_persist,
                         cudaFuncAttributeMaxDynamicSharedMemorySize, DYNSZ);

    zero_state_kernel<<<(Bsz * Hsz + 255) / 256, 256>>>();

    convert_kernel<<<(unsigned)(NCVT / 8 / 256), 256>>>(X, Wihf, Wihb, Whhf, Whhb);

    gemm_x_mma<<<dim3(NTOT / 64, MROWS / 64), 256>>>(bihf, bhhf, bihb, bhhb);

    lstm_persist<<<128, 256, DYNSZ>>>(out);

    proj_kernel<<<dim3(Hsz / 64, 2), 128>>>(
        fhW, fhb, fcW, fcb, out + (size_t)Bsz * Tlen * 2 * Hsz);
}

// round 7
// speedup vs baseline: 6.2592x; 1.0063x over previous
#include <cuda_runtime.h>
#include <cuda_fp16.h>
#include <cstdint>
#include <cstddef>

#define Bsz   64
#define Tlen  512
#define DIN   512
#define Hsz   1024
#define G4H   4096
#define NTOT  8192
#define MROWS 32768

// ---------------------------------------------------------------------------
// Persistent scratch
// ---------------------------------------------------------------------------
__device__ __half   g_G16[(size_t)MROWS * NTOT];   // gate preactivations (x-part + bias)
__device__ __half   g_h_half[2][2][Bsz * Hsz];     // [parity][dir]
__device__ float    g_hT[2][Bsz * Hsz];
__device__ float    g_cT[2][Bsz * Hsz];
__device__ __half   g_X_h[(size_t)MROWS * DIN];
__device__ __half   g_Wih_h[(size_t)NTOT * DIN];
__device__ __half   g_Whh_h[2][(size_t)G4H * Hsz];
__device__ unsigned g_flags[128 * 32];

__global__ void zero_state_kernel() {
    int i = blockIdx.x * blockDim.x + threadIdx.x;
    if (i < Bsz * Hsz) {
        g_h_half[0][0][i] = __float2half(0.f);
        g_h_half[0][1][i] = __float2half(0.f);
    }
    if (i < 128 * 32) g_flags[i] = 0u;
}

// ---------------------------------------------------------------------------
// Helpers
// ---------------------------------------------------------------------------
__device__ __forceinline__ void mma_f16(float* c, const uint32_t* a, const uint32_t* b) {
    asm volatile(
        "mma.sync.aligned.m16n8k16.row.col.f32.f16.f16.f32 "
        "{%0,%1,%2,%3},{%4,%5,%6,%7},{%8,%9},{%0,%1,%2,%3};"
        : "+f"(c[0]), "+f"(c[1]), "+f"(c[2]), "+f"(c[3])
        : "r"(a[0]), "r"(a[1]), "r"(a[2]), "r"(a[3]), "r"(b[0]), "r"(b[1]));
}
__device__ __forceinline__ void cp16(void* smem, const void* g) {
    uint32_t sa = (uint32_t)__cvta_generic_to_shared(smem);
    asm volatile("cp.async.ca.shared.global [%0], [%1], 16;" :: "r"(sa), "l"(g));
}
#define CP_COMMIT() asm volatile("cp.async.commit_group;")
#define CP_WAIT2()  asm volatile("cp.async.wait_group 2;")
#define CP_WAIT0()  asm volatile("cp.async.wait_group 0;")

// ---------------------------------------------------------------------------
// One-time fp16 conversion
// ---------------------------------------------------------------------------
#define NX    ((size_t)MROWS * DIN)
#define NWIH1 ((size_t)G4H * DIN)
#define NWHH1 ((size_t)G4H * Hsz)
#define NCVT  (NX + 2 * NWIH1 + 2 * NWHH1)
__global__ __launch_bounds__(256) void convert_kernel(
    const float* __restrict__ X,
    const float* __restrict__ Wihf, const float* __restrict__ Wihb,
    const float* __restrict__ Whhf, const float* __restrict__ Whhb)
{
    size_t base = ((size_t)blockIdx.x * 256 + threadIdx.x) * 8;
    const float* src;
    __half* dst;
    if (base < NX)                        { src = X + base;                         dst = g_X_h + base; }
    else if (base < NX + NWIH1)           { size_t o = base - NX;                   src = Wihf + o; dst = g_Wih_h + o; }
    else if (base < NX + 2 * NWIH1)       { size_t o = base - NX - NWIH1;           src = Wihb + o; dst = g_Wih_h + NWIH1 + o; }
    else if (base < NX + 2*NWIH1 + NWHH1) { size_t o = base - NX - 2*NWIH1;         src = Whhf + o; dst = g_Whh_h[0] + o; }
    else                                  { size_t o = base - NX - 2*NWIH1 - NWHH1; src = Whhb + o; dst = g_Whh_h[1] + o; }
    float4 v0 = ((const float4*)src)[0];
    float4 v1 = ((const float4*)src)[1];
    __half2 h0 = __floats2half2_rn(v0.x, v0.y);
    __half2 h1 = __floats2half2_rn(v0.z, v0.w);
    __half2 h2 = __floats2half2_rn(v1.x, v1.y);
    __half2 h3 = __floats2half2_rn(v1.z, v1.w);
    uint4 u;
    u.x = *(uint32_t*)&h0; u.y = *(uint32_t*)&h1;
    u.z = *(uint32_t*)&h2; u.w = *(uint32_t*)&h3;
    *(uint4*)dst = u;
}

// ---------------------------------------------------------------------------
// Phase 1: G = X @ [Wf|Wb]^T + bias  (M=32768, N=8192, K=512), fp16 MMA
// 128x128 tile, BK=32, 4-stage cp.async, 256 threads, 8 warps (2m x 4n, 64x32)
// ---------------------------------------------------------------------------
#define P1ST    40                  // halfs per smem row (32 + 8 pad)
#define P1STAGE (128 * P1ST)        // halfs per stage per matrix
#define P1DYN   (8 * P1STAGE * 2)   // 81,920 B

__global__ __launch_bounds__(256) void gemm_x_mma(
    const float* __restrict__ bihf, const float* __restrict__ bhhf,
    const float* __restrict__ bihb, const float* __restrict__ bhhb)
{
    extern __shared__ __half p1s[];
    __half* asb = p1s;
    __half* bsb = p1s + 4 * P1STAGE;

    const int n0  = blockIdx.x * 128;
    const int m0  = blockIdx.y * 128;
    const int tid = threadIdx.x;
    const int wid = tid >> 5, lane = tid & 31;
    const int warp_m = wid & 1, warp_n = wid >> 1;     // 64-row, 32-col tiles
    const int groupID = lane >> 2, tig = lane & 3;

    // load coords: 2 A + 2 B 16B-chunks per thread per stage
    const int i0 = tid * 2, i1 = tid * 2 + 1;
    const int r0l = i0 >> 2, u0l = (i0 & 3) << 3;
    const int r1l = i1 >> 2, u1l = (i1 & 3) << 3;
    const __half* At0 = g_X_h   + (size_t)(m0 + r0l) * DIN + u0l;
    const __half* At1 = g_X_h   + (size_t)(m0 + r1l) * DIN + u1l;
    const __half* Bt0 = g_Wih_h + (size_t)(n0 + r0l) * DIN + u0l;
    const __half* Bt1 = g_Wih_h + (size_t)(n0 + r1l) * DIN + u1l;

    float acc[4][4][4];
#pragma unroll
    for (int mf = 0; mf < 4; mf++)
#pragma unroll
        for (int nf = 0; nf < 4; nf++)
#pragma unroll
            for (int i = 0; i < 4; i++) acc[mf][nf][i] = 0.f;

#define P1_LOAD(st, c)                                                \
    { int k0 = (c) * 32;                                              \
      cp16(&asb[(st) * P1STAGE + r0l * P1ST + u0l], At0 + k0);        \
      cp16(&asb[(st) * P1STAGE + r1l * P1ST + u1l], At1 + k0);        \
      cp16(&bsb[(st) * P1STAGE + r0l * P1ST + u0l], Bt0 + k0);        \
      cp16(&bsb[(st) * P1STAGE + r1l * P1ST + u1l], Bt1 + k0);        \
      CP_COMMIT(); }

    P1_LOAD(0, 0) P1_LOAD(1, 1) P1_LOAD(2, 2)
    const int NIT = DIN / 32;   // 16
    for (int it = 0; it < NIT; it++) {
        CP_WAIT2();
        __syncthreads();
        if (it + 3 < NIT) P1_LOAD((it + 3) & 3, it + 3)
        else              CP_COMMIT();
        const __half* A = asb + (it & 3) * P1STAGE;
        const __half* B = bsb + (it & 3) * P1STAGE;
#pragma unroll
        for (int ks = 0; ks < 2; ks++) {
            const int kk = ks * 16;
            uint32_t av[4][4], bv[4][2];
#pragma unroll
            for (int mf = 0; mf < 4; mf++) {
                int row = warp_m * 64 + mf * 16 + groupID;
                const uint32_t* ap  = (const uint32_t*)(A + row * P1ST + kk + 2 * tig);
                const uint32_t* ap2 = (const uint32_t*)(A + (row + 8) * P1ST + kk + 2 * tig);
                av[mf][0] = ap[0];  av[mf][2] = ap[4];
                av[mf][1] = ap2[0]; av[mf][3] = ap2[4];
            }
#pragma unroll
            for (int nf = 0; nf < 4; nf++) {
                int n = warp_n * 32 + nf * 8 + groupID;
                const uint32_t* bp = (const uint32_t*)(B + n * P1ST + kk + 2 * tig);
                bv[nf][0] = bp[0];
                bv[nf][1] = bp[4];
            }
#pragma unroll
            for (int mf = 0; mf < 4; mf++)
#pragma unroll
                for (int nf = 0; nf < 4; nf++)
                    mma_f16(acc[mf][nf], av[mf], bv[nf]);
        }
    }

    // Epilogue: bias + fp16 store
#pragma unroll
    for (int nf = 0; nf < 4; nf++) {
        int c0 = warp_n * 32 + nf * 8 + 2 * tig;
        int n  = n0 + c0;
        float bias0, bias1;
        if (n < G4H) { bias0 = bihf[n] + bhhf[n]; bias1 = bihf[n + 1] + bhhf[n + 1]; }
        else         { bias0 = bihb[n - G4H] + bhhb[n - G4H];
                       bias1 = bihb[n + 1 - G4H] + bhhb[n + 1 - G4H]; }
#pragma unroll
        for (int mf = 0; mf < 4; mf++) {
            int r0 = m0 + warp_m * 64 + mf * 16 + groupID;
            __half2 v0 = __floats2half2_rn(acc[mf][nf][0] + bias0, acc[mf][nf][1] + bias1);
            __half2 v1 = __floats2half2_rn(acc[mf][nf][2] + bias0, acc[mf][nf][3] + bias1);
            *(__half2*)&g_G16[(size_t)r0 * NTOT + n]       = v0;
            *(__half2*)&g_G16[(size_t)(r0 + 8) * NTOT + n] = v1;
        }
    }
}

// ---------------------------------------------------------------------------
// Phase 2: PERSISTENT LSTM. 128 CTAs (1/SM), 256 threads, K-split-2:
// warps 0-3: k in [0,512), warps 4-7: k in [512,1024); each group 2x2 warps
// of 32x32 tiles over the 64(batch) x 64(4g x 16h) output. W slice resident.
// ---------------------------------------------------------------------------
#define WST    1032                       // halfs per W row (1024 + 8 pad)
#define WBYTES (64 * WST * 2)             // 132,096
#define HSTR   72                         // halfs per h-stage row (64 + 8 pad)
#define HSTAGE (64 * HSTR)                // halfs per stage (both k-groups)
#define P2DYN  (WBYTES + 4 * HSTAGE * 2)  // +36,864 = 168,960 B

__global__ __launch_bounds__(256, 1) void lstm_persist(float* __restrict__ out)
{
    extern __shared__ char smraw[];
    __half* ws  = (__half*)smraw;                    // [64][WST]
    __half* hs  = (__half*)(smraw + WBYTES);         // [4][HSTAGE]
    float*  GtA = (float*)(smraw + WBYTES);          // overlay [64][68]
    float*  GtB = GtA + 64 * 68;

    const int bid = blockIdx.x;
    const int dir = bid >> 6;
    const int hb  = (bid & 63) << 4;
    const int tid = threadIdx.x;
    const int wid = tid >> 5, lane = tid & 31;
    const int grp    = wid >> 2;          // k-group
    const int warp_m = wid & 1;           // 32-row
    const int warp_n = (wid >> 1) & 1;    // 32-col
    const int groupID = lane >> 2, tig = lane & 3;

    // ---- W slice resident load (once) ----
    {
        int r = tid >> 2, u = (tid & 3) << 3;
        int wrow = ((r >> 4) << 10) + hb + (r & 15);
        const __half* src = g_Whh_h[dir] + (size_t)wrow * Hsz;
#pragma unroll
        for (int i = 0; i < 32; i++)
            cp16(&ws[r * WST + u + i * 32], src + u + i * 32);
        CP_COMMIT();
    }
    CP_WAIT0();
    __syncthreads();

    // h-stage load coords: 2 chunks/thread: row 0..63, u = half-col 0..56
    const int i0 = tid * 2, i1 = tid * 2 + 1;
    const int hr0 = i0 >> 3, hu0 = (i0 & 7) << 3;
    const int hr1 = i1 >> 3, hu1 = (i1 & 7) << 3;
    const int hk0 = (hu0 & 31) + ((hu0 & 32) ? 512 : 0);
    const int hk1 = (hu1 & 31) + ((hu1 & 32) ? 512 : 0);

    float cv[4];
#pragma unroll
    for (int q = 0; q < 4; q++) cv[q] = 0.f;

    const __half* __restrict__ Gp = g_G16;

    for (int s = 0; s < Tlen; s++) {
        const int par  = s & 1;
        const int t_in = dir ? (Tlen - 1 - s) : s;
        const __half* Ht = g_h_half[par][dir];

#define H_LOAD(st, c)                                                            \
        { cp16(&hs[(st) * HSTAGE + hr0 * HSTR + hu0], Ht + hr0 * Hsz + hk0 + (c) * 32); \
          cp16(&hs[(st) * HSTAGE + hr1 * HSTR + hu1], Ht + hr1 * Hsz + hk1 + (c) * 32); \
          CP_COMMIT(); }

        H_LOAD(0, 0) H_LOAD(1, 1) H_LOAD(2, 2)

        // Prefetch gate-x preactivations (overlap with GEMM)
        float gx4[4][4];
#pragma unroll
        for (int q = 0; q < 4; q++) {
            int e = tid + q * 256;
            int b = e >> 4, j = e & 15, h = hb + j;
            const __half* gx = Gp + ((size_t)b * Tlen + t_in) * NTOT + dir * G4H + h;
            gx4[q][0] = __half2float(__ldg(gx));
            gx4[q][1] = __half2float(__ldg(gx + Hsz));
            gx4[q][2] = __half2float(__ldg(gx + 2 * Hsz));
            gx4[q][3] = __half2float(__ldg(gx + 3 * Hsz));
        }

        float acc[2][4][4];
#pragma unroll
        for (int mf = 0; mf < 2; mf++)
#pragma unroll
            for (int nf = 0; nf < 4; nf++)
#pragma unroll
                for (int i = 0; i < 4; i++) acc[mf][nf][i] = 0.f;

        for (int it = 0; it < 16; it++) {
            CP_WAIT2();
            __syncthreads();
            if (it + 3 < 16) H_LOAD((it + 3) & 3, it + 3)
            else             CP_COMMIT();
            const __half* A = hs + (it & 3) * HSTAGE;
#pragma unroll
            for (int ks = 0; ks < 2; ks++) {
                const int kk = ks * 16;
                uint32_t av[2][4], bv[4][2];
#pragma unroll
                for (int mf = 0; mf < 2; mf++) {
                    int row = warp_m * 32 + mf * 16 + groupID;
                    const uint32_t* ap  =
                        (const uint32_t*)(A + row * HSTR + grp * 32 + kk + 2 * tig);
                    const uint32_t* ap2 =
                        (const uint32_t*)(A + (row + 8) * HSTR + grp * 32 + kk + 2 * tig);
                    av[mf][0] = ap[0];  av[mf][2] = ap[4];
                    av[mf][1] = ap2[0]; av[mf][3] = ap2[4];
                }
#pragma unroll
                for (int nf = 0; nf < 4; nf++) {
                    int n = warp_n * 32 + nf * 8 + groupID;
                    const uint32_t* bp =
                        (const uint32_t*)(ws + n * WST + grp * 512 + it * 32 + kk + 2 * tig);
                    bv[nf][0] = bp[0];
                    bv[nf][1] = bp[4];
                }
#pragma unroll
                for (int mf = 0; mf < 2; mf++)
#pragma unroll
                    for (int nf = 0; nf < 4; nf++)
                        mma_f16(acc[mf][nf], av[mf], bv[nf]);
            }
        }
        __syncthreads();   // all stage reads done before Gt overlay

        // K-group reduction via smem
        float* Gt = grp ? GtB : GtA;
#pragma unroll
        for (int mf = 0; mf < 2; mf++) {
            int r0 = warp_m * 32 + mf * 16 + groupID;
#pragma unroll
            for (int nf = 0; nf < 4; nf++) {
                int c0 = warp_n * 32 + nf * 8 + 2 * tig;
                Gt[r0 * 68 + c0]           = acc[mf][nf][0];
                Gt[r0 * 68 + c0 + 1]       = acc[mf][nf][1];
                Gt[(r0 + 8) * 68 + c0]     = acc[mf][nf][2];
                Gt[(r0 + 8) * 68 + c0 + 1] = acc[mf][nf][3];
            }
        }
        __syncthreads();

        // Cell update
        __half* hnewh = g_h_half[par ^ 1][dir];
#pragma unroll
        for (int q = 0; q < 4; q++) {
            int e = tid + q * 256;
            int b = e >> 4, j = e & 15, h = hb + j;
            float gi = GtA[b * 68 + j]      + GtB[b * 68 + j]      + gx4[q][0];
            float gf = GtA[b * 68 + 16 + j] + GtB[b * 68 + 16 + j] + gx4[q][1];
            float gg = GtA[b * 68 + 32 + j] + GtB[b * 68 + 32 + j] + gx4[q][2];
            float go = GtA[b * 68 + 48 + j] + GtB[b * 68 + 48 + j] + gx4[q][3];

            float si = 1.f / (1.f + expf(-gi));
            float sf = 1.f / (1.f + expf(-gf));
            float so = 1.f / (1.f + expf(-go));
            float tg = tanhf(gg);

            float cn = sf * cv[q] + si * tg;
            cv[q] = cn;
            float hn = so * tanhf(cn);
            hnewh[b * Hsz + h] = __float2half_rn(hn);
            out[((size_t)b * Tlen + s) * (2 * Hsz) + dir * Hsz + h] = hn;
            if (s == Tlen - 1) {
                g_hT[dir][b * Hsz + h] = hn;
                g_cT[dir][b * Hsz + h] = cn;
            }
        }
        __syncthreads();

        // ---- Per-direction grid barrier (64 CTAs each) ----
        if (tid == 0) {
            unsigned* fl = &g_flags[bid * 32];
            asm volatile("st.release.gpu.u32 [%0], %1;"
                         :: "l"(fl), "r"((unsigned)(s + 1)) : "memory");
        }
        if (tid < 64) {
            unsigned* fl = &g_flags[(dir * 64 + tid) * 32];
            unsigned v;
            do {
                asm volatile("ld.acquire.gpu.u32 %0, [%1];" : "=r"(v) : "l"(fl) : "memory");
                if (v < (unsigned)(s + 1)) __nanosleep(40);
            } while (v < (unsigned)(s + 1));
        }
        __syncthreads();
    }
}

// ---------------------------------------------------------------------------
// Phase 3: decoder-init projections
// ---------------------------------------------------------------------------
__global__ __launch_bounds__(128) void proj_kernel(
    const float* __restrict__ fhW, const float* __restrict__ fhb,
    const float* __restrict__ fcW, const float* __restrict__ fcb,
    float* __restrict__ out2)
{
    __shared__ float As[64][17];
    __shared__ float Bs[64][17];

    const int which = blockIdx.y;
    const float* __restrict__ W    = which ? fcW : fhW;
    const float* __restrict__ bias = which ? fcb : fhb;
    const float* __restrict__ src0 = which ? g_cT[0] : g_hT[0];
    const float* __restrict__ src1 = which ? g_cT[1] : g_hT[1];

    const int d0  = blockIdx.x * 64;
    const int tid = threadIdx.x;
    const int ty  = tid >> 4;
    const int tx  = tid & 15;

    float acc[8][4];
#pragma unroll
    for (int r = 0; r < 8; r++)
#pragma unroll
        for (int c = 0; c < 4; c++) acc[r][c] = 0.f;

    for (int k0 = 0; k0 < 2 * Hsz; k0 += 16) {
#pragma unroll
        for (int i = 0; i < 2; i++) {
            int idx = tid * 2 + i;
            int row = idx >> 2;
            int c4  = (idx & 3) << 2;
            int k   = k0 + c4;
            const float* sp = (k < Hsz) ? &src0[row * Hsz + k]
                                        : &src1[row * Hsz + k - Hsz];
            float4 v = *(const float4*)sp;
            As[row][c4 + 0] = v.x; As[row][c4 + 1] = v.y;
            As[row][c4 + 2] = v.z; As[row][c4 + 3] = v.w;

            float4 w = *(const float4*)&W[(size_t)(d0 + row) * (2 * Hsz) + k0 + c4];
            Bs[row][c4 + 0] = w.x; Bs[row][c4 + 1] = w.y;
            Bs[row][c4 + 2] = w.z; Bs[row][c4 + 3] = w.w;
        }
        __syncthreads();
#pragma unroll
        for (int kk = 0; kk < 16; kk++) {
            float a[8], b[4];
#pragma unroll
            for (int r = 0; r < 8; r++) a[r] = As[ty * 8 + r][kk];
#pragma unroll
            for (int c = 0; c < 4; c++) b[c] = Bs[tx + 16 * c][kk];
#pragma unroll
            for (int r = 0; r < 8; r++)
#pragma unroll
                for (int c = 0; c < 4; c++) acc[r][c] += a[r] * b[c];
        }
        __syncthreads();
    }

#pragma unroll
    for (int c = 0; c < 4; c++) {
        int d = d0 + tx + 16 * c;
        float bv = bias[d];
#pragma unroll
        for (int r = 0; r < 8; r++) {
            int b = ty * 8 + r;
            out2[(size_t)which * (Bsz * Hsz) + b * Hsz + d] = tanhf(acc[r][c] + bv);
        }
    }
}

// ---------------------------------------------------------------------------
// Launch
// ---------------------------------------------------------------------------
extern "C" void kernel_launch(void* const* d_in, const int* in_sizes, int n_in,
                              void* d_out, int out_size)
{
    const float* X    = (const float*)d_in[0];
    const float* Wihf = (const float*)d_in[1];
    const float* Whhf = (const float*)d_in[2];
    const float* bihf = (const float*)d_in[3];
    const float* bhhf = (const float*)d_in[4];
    const float* Wihb = (const float*)d_in[5];
    const float* Whhb = (const float*)d_in[6];
    const float* bihb = (const float*)d_in[7];
    const float* bhhb = (const float*)d_in[8];
    const float* fcW  = (const float*)d_in[9];
    const float* fcb  = (const float*)d_in[10];
    const float* fhW  = (const float*)d_in[11];
    const float* fhb  = (const float*)d_in[12];
    float* out = (float*)d_out;

    cudaFuncSetAttribute(gemm_x_mma,
                         cudaFuncAttributeMaxDynamicSharedMemorySize, P1DYN);
    cudaFuncSetAttribute(lstm_persist,
                         cudaFuncAttributeMaxDynamicSharedMemorySize, P2DYN);

    zero_state_kernel<<<(Bsz * Hsz + 255) / 256, 256>>>();

    convert_kernel<<<(unsigned)(NCVT / 8 / 256), 256>>>(X, Wihf, Wihb, Whhf, Whhb);

    gemm_x_mma<<<dim3(NTOT / 128, MROWS / 128), 256, P1DYN>>>(bihf, bhhf, bihb, bhhb);

    lstm_persist<<<128, 256, P2DYN>>>(out);

    proj_kernel<<<dim3(Hsz / 64, 2), 128>>>(
        fhW, fhb, fcW, fcb, out + (size_t)Bsz * Tlen * 2 * Hsz);
}

// round 8
// speedup vs baseline: 7.2509x; 1.1584x over previous
#include <cuda_runtime.h>
#include <cuda_fp16.h>
#include <cstdint>
#include <cstddef>

#define Bsz   64
#define Tlen  512
#define DIN   512
#define Hsz   1024
#define G4H   4096
#define NTOT  8192
#define MROWS 32768

// ---------------------------------------------------------------------------
// Persistent scratch
// ---------------------------------------------------------------------------
__device__ __half   g_G16[(size_t)MROWS * NTOT];
__device__ __half   g_h_half[2][2][Bsz * Hsz];
__device__ float    g_hT[2][Bsz * Hsz];
__device__ float    g_cT[2][Bsz * Hsz];
__device__ __half   g_X_h[(size_t)MROWS * DIN];
__device__ __half   g_Wih_h[(size_t)NTOT * DIN];
__device__ __half   g_Whh_h[2][(size_t)G4H * Hsz];
__device__ unsigned g_flags[128 * 32];

__global__ void zero_state_kernel() {
    int i = blockIdx.x * blockDim.x + threadIdx.x;
    if (i < Bsz * Hsz) {
        g_h_half[0][0][i] = __float2half(0.f);
        g_h_half[0][1][i] = __float2half(0.f);
    }
    if (i < 128 * 32) g_flags[i] = 0u;
}

// ---------------------------------------------------------------------------
// Helpers
// ---------------------------------------------------------------------------
__device__ __forceinline__ void mma_f16(float* c, const uint32_t* a, const uint32_t* b) {
    asm volatile(
        "mma.sync.aligned.m16n8k16.row.col.f32.f16.f16.f32 "
        "{%0,%1,%2,%3},{%4,%5,%6,%7},{%8,%9},{%0,%1,%2,%3};"
        : "+f"(c[0]), "+f"(c[1]), "+f"(c[2]), "+f"(c[3])
        : "r"(a[0]), "r"(a[1]), "r"(a[2]), "r"(a[3]), "r"(b[0]), "r"(b[1]));
}
__device__ __forceinline__ void cp16(void* smem, const void* g) {
    uint32_t sa = (uint32_t)__cvta_generic_to_shared(smem);
    asm volatile("cp.async.ca.shared.global [%0], [%1], 16;" :: "r"(sa), "l"(g));
}
#define CP_COMMIT() asm volatile("cp.async.commit_group;")
#define CP_WAIT2()  asm volatile("cp.async.wait_group 2;")
#define CP_WAIT0()  asm volatile("cp.async.wait_group 0;")

__device__ __forceinline__ uint32_t smem_u32(const void* p) {
    return (uint32_t)__cvta_generic_to_shared(p);
}
__device__ __forceinline__ void mbar_init(uint32_t addr, uint32_t cnt) {
    asm volatile("mbarrier.init.shared.b64 [%0], %1;" :: "r"(addr), "r"(cnt) : "memory");
}
__device__ __forceinline__ void mbar_expect(uint32_t addr, uint32_t bytes) {
    asm volatile("mbarrier.arrive.expect_tx.shared.b64 _, [%0], %1;"
                 :: "r"(addr), "r"(bytes) : "memory");
}
__device__ __forceinline__ void mbar_wait(uint32_t addr, uint32_t parity) {
    uint32_t done;
    do {
        asm volatile(
            "{\n\t.reg .pred p;\n\t"
            "mbarrier.try_wait.parity.acquire.cta.shared::cta.b64 p, [%1], %2, 0x989680;\n\t"
            "selp.b32 %0, 1, 0, p;\n\t}"
            : "=r"(done) : "r"(addr), "r"(parity) : "memory");
    } while (!done);
}
__device__ __forceinline__ void bulk_g2s(uint32_t dst, const void* src,
                                         uint32_t bytes, uint32_t mbar) {
    asm volatile(
        "cp.async.bulk.shared::cluster.global.mbarrier::complete_tx::bytes "
        "[%0], [%1], %2, [%3];"
        :: "r"(dst), "l"(src), "r"(bytes), "r"(mbar) : "memory");
}
#define LDSM4(r0, r1, r2, r3, addr) \
    asm volatile("ldmatrix.sync.aligned.m8n8.x4.shared.b16 {%0,%1,%2,%3}, [%4];" \
                 : "=r"(r0), "=r"(r1), "=r"(r2), "=r"(r3) : "r"(addr))

// ---------------------------------------------------------------------------
// One-time fp16 conversion
// ---------------------------------------------------------------------------
#define NX    ((size_t)MROWS * DIN)
#define NWIH1 ((size_t)G4H * DIN)
#define NWHH1 ((size_t)G4H * Hsz)
#define NCVT  (NX + 2 * NWIH1 + 2 * NWHH1)
__global__ __launch_bounds__(256) void convert_kernel(
    const float* __restrict__ X,
    const float* __restrict__ Wihf, const float* __restrict__ Wihb,
    const float* __restrict__ Whhf, const float* __restrict__ Whhb)
{
    size_t base = ((size_t)blockIdx.x * 256 + threadIdx.x) * 8;
    const float* src;
    __half* dst;
    if (base < NX)                        { src = X + base;                         dst = g_X_h + base; }
    else if (base < NX + NWIH1)           { size_t o = base - NX;                   src = Wihf + o; dst = g_Wih_h + o; }
    else if (base < NX + 2 * NWIH1)       { size_t o = base - NX - NWIH1;           src = Wihb + o; dst = g_Wih_h + NWIH1 + o; }
    else if (base < NX + 2*NWIH1 + NWHH1) { size_t o = base - NX - 2*NWIH1;         src = Whhf + o; dst = g_Whh_h[0] + o; }
    else                                  { size_t o = base - NX - 2*NWIH1 - NWHH1; src = Whhb + o; dst = g_Whh_h[1] + o; }
    float4 v0 = ((const float4*)src)[0];
    float4 v1 = ((const float4*)src)[1];
    __half2 h0 = __floats2half2_rn(v0.x, v0.y);
    __half2 h1 = __floats2half2_rn(v0.z, v0.w);
    __half2 h2 = __floats2half2_rn(v1.x, v1.y);
    __half2 h3 = __floats2half2_rn(v1.z, v1.w);
    uint4 u;
    u.x = *(uint32_t*)&h0; u.y = *(uint32_t*)&h1;
    u.z = *(uint32_t*)&h2; u.w = *(uint32_t*)&h3;
    *(uint4*)dst = u;
}

// ---------------------------------------------------------------------------
// Phase 1 (unchanged): G = X @ [Wf|Wb]^T + bias, fp16 MMA, 128x128, 4-stage
// ---------------------------------------------------------------------------
#define P1ST    40
#define P1STAGE (128 * P1ST)
#define P1DYN   (8 * P1STAGE * 2)

__global__ __launch_bounds__(256) void gemm_x_mma(
    const float* __restrict__ bihf, const float* __restrict__ bhhf,
    const float* __restrict__ bihb, const float* __restrict__ bhhb)
{
    extern __shared__ __half p1s[];
    __half* asb = p1s;
    __half* bsb = p1s + 4 * P1STAGE;

    const int n0  = blockIdx.x * 128;
    const int m0  = blockIdx.y * 128;
    const int tid = threadIdx.x;
    const int wid = tid >> 5, lane = tid & 31;
    const int warp_m = wid & 1, warp_n = wid >> 1;
    const int groupID = lane >> 2, tig = lane & 3;

    const int i0 = tid * 2, i1 = tid * 2 + 1;
    const int r0l = i0 >> 2, u0l = (i0 & 3) << 3;
    const int r1l = i1 >> 2, u1l = (i1 & 3) << 3;
    const __half* At0 = g_X_h   + (size_t)(m0 + r0l) * DIN + u0l;
    const __half* At1 = g_X_h   + (size_t)(m0 + r1l) * DIN + u1l;
    const __half* Bt0 = g_Wih_h + (size_t)(n0 + r0l) * DIN + u0l;
    const __half* Bt1 = g_Wih_h + (size_t)(n0 + r1l) * DIN + u1l;

    float acc[4][4][4];
#pragma unroll
    for (int mf = 0; mf < 4; mf++)
#pragma unroll
        for (int nf = 0; nf < 4; nf++)
#pragma unroll
            for (int i = 0; i < 4; i++) acc[mf][nf][i] = 0.f;

#define P1_LOAD(st, c)                                                \
    { int k0 = (c) * 32;                                              \
      cp16(&asb[(st) * P1STAGE + r0l * P1ST + u0l], At0 + k0);        \
      cp16(&asb[(st) * P1STAGE + r1l * P1ST + u1l], At1 + k0);        \
      cp16(&bsb[(st) * P1STAGE + r0l * P1ST + u0l], Bt0 + k0);        \
      cp16(&bsb[(st) * P1STAGE + r1l * P1ST + u1l], Bt1 + k0);        \
      CP_COMMIT(); }

    P1_LOAD(0, 0) P1_LOAD(1, 1) P1_LOAD(2, 2)
    const int NIT = DIN / 32;
    for (int it = 0; it < NIT; it++) {
        CP_WAIT2();
        __syncthreads();
        if (it + 3 < NIT) P1_LOAD((it + 3) & 3, it + 3)
        else              CP_COMMIT();
        const __half* A = asb + (it & 3) * P1STAGE;
        const __half* B = bsb + (it & 3) * P1STAGE;
#pragma unroll
        for (int ks = 0; ks < 2; ks++) {
            const int kk = ks * 16;
            uint32_t av[4][4], bv[4][2];
#pragma unroll
            for (int mf = 0; mf < 4; mf++) {
                int row = warp_m * 64 + mf * 16 + groupID;
                const uint32_t* ap  = (const uint32_t*)(A + row * P1ST + kk + 2 * tig);
                const uint32_t* ap2 = (const uint32_t*)(A + (row + 8) * P1ST + kk + 2 * tig);
                av[mf][0] = ap[0];  av[mf][2] = ap[4];
                av[mf][1] = ap2[0]; av[mf][3] = ap2[4];
            }
#pragma unroll
            for (int nf = 0; nf < 4; nf++) {
                int n = warp_n * 32 + nf * 8 + groupID;
                const uint32_t* bp = (const uint32_t*)(B + n * P1ST + kk + 2 * tig);
                bv[nf][0] = bp[0];
                bv[nf][1] = bp[4];
            }
#pragma unroll
            for (int mf = 0; mf < 4; mf++)
#pragma unroll
                for (int nf = 0; nf < 4; nf++)
                    mma_f16(acc[mf][nf], av[mf], bv[nf]);
        }
    }

#pragma unroll
    for (int nf = 0; nf < 4; nf++) {
        int c0 = warp_n * 32 + nf * 8 + 2 * tig;
        int n  = n0 + c0;
        float bias0, bias1;
        if (n < G4H) { bias0 = bihf[n] + bhhf[n]; bias1 = bihf[n + 1] + bhhf[n + 1]; }
        else         { bias0 = bihb[n - G4H] + bhhb[n - G4H];
                       bias1 = bihb[n + 1 - G4H] + bhhb[n + 1 - G4H]; }
#pragma unroll
        for (int mf = 0; mf < 4; mf++) {
            int r0 = m0 + warp_m * 64 + mf * 16 + groupID;
            __half2 v0 = __floats2half2_rn(acc[mf][nf][0] + bias0, acc[mf][nf][1] + bias1);
            __half2 v1 = __floats2half2_rn(acc[mf][nf][2] + bias0, acc[mf][nf][3] + bias1);
            *(__half2*)&g_G16[(size_t)r0 * NTOT + n]       = v0;
            *(__half2*)&g_G16[(size_t)(r0 + 8) * NTOT + n] = v1;
        }
    }
}

// ---------------------------------------------------------------------------
// Phase 2: PERSISTENT LSTM, bulk-DMA + ldmatrix.
// ---------------------------------------------------------------------------
#define WROWB  2064
#define WBYTES (64 * WROWB)
#define HCHB   33024
#define HOFF   WBYTES
#define GTOFF  (HOFF + 2 * HCHB)
#define GXOFF  (GTOFF + 4 * 16 * 68 * 4)
#define P2DYN  (GXOFF + 64 * 72 * 2)

__global__ __launch_bounds__(256, 1) void lstm_persist(float* __restrict__ out)
{
    extern __shared__ char smraw[];
    __half* ws  = (__half*)smraw;
    float*  Gt  = (float*)(smraw + GTOFF);
    __half* gxs = (__half*)(smraw + GXOFF);
    __shared__ __align__(8) uint64_t s_mbar[2];

    const uint32_t sm0    = smem_u32(smraw);
    const uint32_t hbu0   = sm0 + HOFF;
    const uint32_t hbu1   = sm0 + HOFF + HCHB;
    const uint32_t wsu    = sm0;
    const uint32_t mb0    = smem_u32(&s_mbar[0]);
    const uint32_t mb1    = smem_u32(&s_mbar[1]);

    const int bid = blockIdx.x;
    const int dir = bid >> 6;
    const int hb  = (bid & 63) << 4;
    const int tid = threadIdx.x;
    const int wid = tid >> 5, lane = tid & 31;
    const int grp = wid >> 1;
    const int nw  = wid & 1;
    const int groupID = lane >> 2, tig = lane & 3;

    if (tid == 0) { mbar_init(mb0, 1); mbar_init(mb1, 1); }

    // ---- W slice resident load (once) ----
    {
        int r = tid >> 2, u = (tid & 3) << 3;
        int wrow = ((r >> 4) << 10) + hb + (r & 15);
        const __half* src = g_Whh_h[dir] + (size_t)wrow * Hsz;
#pragma unroll
        for (int i = 0; i < 32; i++)
            cp16(&ws[r * 1032 + u + i * 32], src + u + i * 32);
        CP_COMMIT();
    }
    CP_WAIT0();
    __syncthreads();

    const uint32_t a_lane  = (uint32_t)((lane & 15) * WROWB + ((lane >> 4) << 4));
    const uint32_t b_lane0 = (uint32_t)((nw * 32 + (lane & 15)) * WROWB + ((lane >> 4) << 4));
    const uint32_t kgrp_b  = (uint32_t)(grp * 512);

    const int o0 = tid * 2, o1 = tid * 2 + 1;
    const int bl = tid >> 4, j = tid & 15;

    float cv[4];
#pragma unroll
    for (int q = 0; q < 4; q++) cv[q] = 0.f;

    for (int s = 0; s < Tlen; s++) {
        const int par  = s & 1;
        const int t_in = dir ? (Tlen - 1 - s) : s;
        const __half* Ht = g_h_half[par][dir];

        // gate-x tile -> smem
        {
            int b0 = o0 >> 3, g0 = (o0 >> 1) & 3, f0 = o0 & 1;
            int b1 = o1 >> 3, g1 = (o1 >> 1) & 3, f1 = o1 & 1;
            cp16(&gxs[b0 * 72 + g0 * 16 + f0 * 8],
                 g_G16 + ((size_t)b0 * Tlen + t_in) * NTOT + dir * G4H + g0 * 1024 + hb + f0 * 8);
            cp16(&gxs[b1 * 72 + g1 * 16 + f1 * 8],
                 g_G16 + ((size_t)b1 * Tlen + t_in) * NTOT + dir * G4H + g1 * 1024 + hb + f1 * 8);
            CP_COMMIT();
        }

        if (tid == 0) {
            mbar_expect(mb0, 32768u);
#pragma unroll
            for (int r = 0; r < 16; r++)
                bulk_g2s(hbu0 + r * WROWB, Ht + (size_t)r * Hsz, 2048u, mb0);
            mbar_expect(mb1, 32768u);
#pragma unroll
            for (int r = 0; r < 16; r++)
                bulk_g2s(hbu1 + r * WROWB, Ht + (size_t)(16 + r) * Hsz, 2048u, mb1);
        }

        for (int sub = 0; sub < 4; sub++) {
            const int buf = sub & 1;
            const int uses = s * 2 + (sub >> 1);
            mbar_wait(buf ? mb1 : mb0, uses & 1);

            float acc[4][4];
#pragma unroll
            for (int nf = 0; nf < 4; nf++)
#pragma unroll
                for (int i = 0; i < 4; i++) acc[nf][i] = 0.f;

            const uint32_t ab = (buf ? hbu1 : hbu0) + a_lane + kgrp_b;
            const uint32_t bb = wsu + b_lane0 + kgrp_b;
#pragma unroll
            for (int ks = 0; ks < 16; ks++) {
                uint32_t a[4], b0r[4], b1r[4];
                LDSM4(a[0], a[1], a[2], a[3], ab + ks * 32);
                LDSM4(b0r[0], b0r[1], b0r[2], b0r[3], bb + ks * 32);
                LDSM4(b1r[0], b1r[1], b1r[2], b1r[3], bb + 16 * WROWB + ks * 32);
                uint32_t p0[2] = { b0r[0], b0r[2] }, p1[2] = { b0r[1], b0r[3] };
                uint32_t p2[2] = { b1r[0], b1r[2] }, p3[2] = { b1r[1], b1r[3] };
                mma_f16(acc[0], a, p0);
                mma_f16(acc[1], a, p1);
                mma_f16(acc[2], a, p2);
                mma_f16(acc[3], a, p3);
            }

#pragma unroll
            for (int nf = 0; nf < 4; nf++) {
                int col = nw * 32 + nf * 8 + 2 * tig;
                float* q0 = &Gt[(grp * 16 + groupID) * 68 + col];
                float* q1 = &Gt[(grp * 16 + groupID + 8) * 68 + col];
                q0[0] = acc[nf][0]; q0[1] = acc[nf][1];
                q1[0] = acc[nf][2]; q1[1] = acc[nf][3];
            }
            if (sub == 0) CP_WAIT0();
            __syncthreads();

            if (sub < 2 && tid == 0) {
                uint32_t mb  = buf ? mb1 : mb0;
                uint32_t hbu = buf ? hbu1 : hbu0;
                mbar_expect(mb, 32768u);
#pragma unroll
                for (int r = 0; r < 16; r++)
                    bulk_g2s(hbu + r * WROWB,
                             Ht + (size_t)((sub + 2) * 16 + r) * Hsz, 2048u, mb);
            }

            {
                int b = sub * 16 + bl;
                int h = hb + j;
                float gi = 0.f, gf = 0.f, gg = 0.f, go = 0.f;
#pragma unroll
                for (int g4 = 0; g4 < 4; g4++) {
                    const float* gr = &Gt[(g4 * 16 + bl) * 68];
                    gi += gr[j];
                    gf += gr[16 + j];
                    gg += gr[32 + j];
                    go += gr[48 + j];
                }
                const __half* gx = &gxs[b * 72];
                gi += __half2float(gx[j]);
                gf += __half2float(gx[16 + j]);
                gg += __half2float(gx[32 + j]);
                go += __half2float(gx[48 + j]);

                float si = 1.f / (1.f + expf(-gi));
                float sf = 1.f / (1.f + expf(-gf));
                float so = 1.f / (1.f + expf(-go));
                float tg = tanhf(gg);

                float cn = sf * cv[sub] + si * tg;
                cv[sub] = cn;
                float hn = so * tanhf(cn);
                g_h_half[par ^ 1][dir][b * Hsz + h] = __float2half_rn(hn);
                out[((size_t)b * Tlen + s) * (2 * Hsz) + dir * Hsz + h] = hn;
                if (s == Tlen - 1) {
                    g_hT[dir][b * Hsz + h] = hn;
                    g_cT[dir][b * Hsz + h] = cn;
                }
            }
            __syncthreads();
        }

        if (tid == 0) {
            asm volatile("fence.proxy.async;" ::: "memory");
            unsigned* fl = &g_flags[bid * 32];
            asm volatile("st.release.gpu.u32 [%0], %1;"
                         :: "l"(fl), "r"((unsigned)(s + 1)) : "memory");
        }
        if (tid < 64) {
            unsigned* fl = &g_flags[(dir * 64 + tid) * 32];
            unsigned v;
            do {
                asm volatile("ld.acquire.gpu.u32 %0, [%1];" : "=r"(v) : "l"(fl) : "memory");
            } while (v < (unsigned)(s + 1));
        }
        __syncthreads();
    }
}

// ---------------------------------------------------------------------------
// Phase 3: decoder-init projections
// ---------------------------------------------------------------------------
__global__ __launch_bounds__(128) void proj_kernel(
    const float* __restrict__ fhW, const float* __restrict__ fhb,
    const float* __restrict__ fcW, const float* __restrict__ fcb,
    float* __restrict__ out2)
{
    __shared__ float As[64][17];
    __shared__ float Bs[64][17];

    const int which = blockIdx.y;
    const float* __restrict__ W    = which ? fcW : fhW;
    const float* __restrict__ bias = which ? fcb : fhb;
    const float* __restrict__ src0 = which ? g_cT[0] : g_hT[0];
    const float* __restrict__ src1 = which ? g_cT[1] : g_hT[1];

    const int d0  = blockIdx.x * 64;
    const int tid = threadIdx.x;
    const int ty  = tid >> 4;
    const int tx  = tid & 15;

    float acc[8][4];
#pragma unroll
    for (int r = 0; r < 8; r++)
#pragma unroll
        for (int c = 0; c < 4; c++) acc[r][c] = 0.f;

    for (int k0 = 0; k0 < 2 * Hsz; k0 += 16) {
#pragma unroll
        for (int i = 0; i < 2; i++) {
            int idx = tid * 2 + i;
            int row = idx >> 2;
            int c4  = (idx & 3) << 2;
            int k   = k0 + c4;
            const float* sp = (k < Hsz) ? &src0[row * Hsz + k]
                                        : &src1[row * Hsz + k - Hsz];
            float4 v = *(const float4*)sp;
            As[row][c4 + 0] = v.x; As[row][c4 + 1] = v.y;
            As[row][c4 + 2] = v.z; As[row][c4 + 3] = v.w;

            float4 w = *(const float4*)&W[(size_t)(d0 + row) * (2 * Hsz) + k0 + c4];
            Bs[row][c4 + 0] = w.x; Bs[row][c4 + 1] = w.y;
            Bs[row][c4 + 2] = w.z; Bs[row][c4 + 3] = w.w;
        }
        __syncthreads();
#pragma unroll
        for (int kk = 0; kk < 16; kk++) {
            float a[8], b[4];
#pragma unroll
            for (int r = 0; r < 8; r++) a[r] = As[ty * 8 + r][kk];
#pragma unroll
            for (int c = 0; c < 4; c++) b[c] = Bs[tx + 16 * c][kk];
#pragma unroll
            for (int r = 0; r < 8; r++)
#pragma unroll
                for (int c = 0; c < 4; c++) acc[r][c] += a[r] * b[c];
        }
        __syncthreads();
    }

#pragma unroll
    for (int c = 0; c < 4; c++) {
        int d = d0 + tx + 16 * c;
        float bv = bias[d];
#pragma unroll
        for (int r = 0; r < 8; r++) {
            int b = ty * 8 + r;
            out2[(size_t)which * (Bsz * Hsz) + b * Hsz + d] = tanhf(acc[r][c] + bv);
        }
    }
}

// ---------------------------------------------------------------------------
// Launch
// ---------------------------------------------------------------------------
extern "C" void kernel_launch(void* const* d_in, const int* in_sizes, int n_in,
                              void* d_out, int out_size)
{
    const float* X    = (const float*)d_in[0];
    const float* Wihf = (const float*)d_in[1];
    const float* Whhf = (const float*)d_in[2];
    const float* bihf = (const float*)d_in[3];
    const float* bhhf = (const float*)d_in[4];
    const float* Wihb = (const float*)d_in[5];
    const float* Whhb = (const float*)d_in[6];
    const float* bihb = (const float*)d_in[7];
    const float* bhhb = (const float*)d_in[8];
    const float* fcW  = (const float*)d_in[9];
    const float* fcb  = (const float*)d_in[10];
    const float* fhW  = (const float*)d_in[11];
    const float* fhb  = (const float*)d_in[12];
    float* out = (float*)d_out;

    cudaFuncSetAttribute(gemm_x_mma,
                         cudaFuncAttributeMaxDynamicSharedMemorySize, P1DYN);
    cudaFuncSetAttribute(lstm_persist,
                         cudaFuncAttributeMaxDynamicSharedMemorySize, P2DYN);

    zero_state_kernel<<<(Bsz * Hsz + 255) / 256, 256>>>();

    convert_kernel<<<(unsigned)(NCVT / 8 / 256), 256>>>(X, Wihf, Wihb, Whhf, Whhb);

    gemm_x_mma<<<dim3(NTOT / 128, MROWS / 128), 256, P1DYN>>>(bihf, bhhf, bihb, bhhb);

    lstm_persist<<<128, 256, P2DYN>>>(out);

    proj_kernel<<<dim3(Hsz / 64, 2), 128>>>(
        fhW, fhb, fcW, fcb, out + (size_t)Bsz * Tlen * 2 * Hsz);
}

// round 9
// speedup vs baseline: 8.5472x; 1.1788x over previous
#include <cuda_runtime.h>
#include <cuda_fp16.h>
#include <cstdint>
#include <cstddef>

#define Bsz   64
#define Tlen  512
#define DIN   512
#define Hsz   1024
#define G4H   4096
#define NTOT  8192
#define MROWS 32768

// ---------------------------------------------------------------------------
// Persistent scratch
// ---------------------------------------------------------------------------
__device__ __half   g_G16[(size_t)MROWS * NTOT];
__device__ __half   g_h_half[2][2][Bsz * Hsz];
__device__ float    g_hT[2][Bsz * Hsz];
__device__ float    g_cT[2][Bsz * Hsz];
__device__ __half   g_X_h[(size_t)MROWS * DIN];
__device__ __half   g_Wih_h[(size_t)NTOT * DIN];
__device__ __half   g_Whh_h[2][(size_t)G4H * Hsz];
__device__ unsigned g_flags[4096];     // [dir][chunk][slice] * 8 spacing

__global__ void zero_state_kernel() {
    int i = blockIdx.x * blockDim.x + threadIdx.x;
    if (i < Bsz * Hsz) {
        g_h_half[0][0][i] = __float2half(0.f);
        g_h_half[0][1][i] = __float2half(0.f);
    }
    if (i < 4096) g_flags[i] = 0u;
}

// ---------------------------------------------------------------------------
// Helpers
// ---------------------------------------------------------------------------
__device__ __forceinline__ void mma_f16(float* c, const uint32_t* a, const uint32_t* b) {
    asm volatile(
        "mma.sync.aligned.m16n8k16.row.col.f32.f16.f16.f32 "
        "{%0,%1,%2,%3},{%4,%5,%6,%7},{%8,%9},{%0,%1,%2,%3};"
        : "+f"(c[0]), "+f"(c[1]), "+f"(c[2]), "+f"(c[3])
        : "r"(a[0]), "r"(a[1]), "r"(a[2]), "r"(a[3]), "r"(b[0]), "r"(b[1]));
}
__device__ __forceinline__ void cp16(void* smem, const void* g) {
    uint32_t sa = (uint32_t)__cvta_generic_to_shared(smem);
    asm volatile("cp.async.ca.shared.global [%0], [%1], 16;" :: "r"(sa), "l"(g));
}
#define CP_COMMIT() asm volatile("cp.async.commit_group;")
#define CP_WAIT2()  asm volatile("cp.async.wait_group 2;")
#define CP_WAIT0()  asm volatile("cp.async.wait_group 0;")

__device__ __forceinline__ uint32_t smem_u32(const void* p) {
    return (uint32_t)__cvta_generic_to_shared(p);
}
__device__ __forceinline__ void mbar_init(uint32_t addr, uint32_t cnt) {
    asm volatile("mbarrier.init.shared.b64 [%0], %1;" :: "r"(addr), "r"(cnt) : "memory");
}
__device__ __forceinline__ void mbar_expect(uint32_t addr, uint32_t bytes) {
    asm volatile("mbarrier.arrive.expect_tx.shared.b64 _, [%0], %1;"
                 :: "r"(addr), "r"(bytes) : "memory");
}
__device__ __forceinline__ void mbar_arrive(uint32_t addr) {
    asm volatile("mbarrier.arrive.shared.b64 _, [%0];" :: "r"(addr) : "memory");
}
__device__ __forceinline__ void mbar_wait(uint32_t addr, uint32_t parity) {
    uint32_t done;
    do {
        asm volatile(
            "{\n\t.reg .pred p;\n\t"
            "mbarrier.try_wait.parity.acquire.cta.shared::cta.b64 p, [%1], %2, 0x989680;\n\t"
            "selp.b32 %0, 1, 0, p;\n\t}"
            : "=r"(done) : "r"(addr), "r"(parity) : "memory");
    } while (!done);
}
__device__ __forceinline__ void bulk_g2s(uint32_t dst, const void* src,
                                         uint32_t bytes, uint32_t mbar) {
    asm volatile(
        "cp.async.bulk.shared::cluster.global.mbarrier::complete_tx::bytes "
        "[%0], [%1], %2, [%3];"
        :: "r"(dst), "l"(src), "r"(bytes), "r"(mbar) : "memory");
}
#define LDSM4(r0, r1, r2, r3, addr) \
    asm volatile("ldmatrix.sync.aligned.m8n8.x4.shared.b16 {%0,%1,%2,%3}, [%4];" \
                 : "=r"(r0), "=r"(r1), "=r"(r2), "=r"(r3) : "r"(addr))
#define BAR1() asm volatile("bar.sync 1, 256;" ::: "memory")

__device__ __forceinline__ float fsig(float x) {
    return __fdividef(1.f, 1.f + __expf(-x));
}
__device__ __forceinline__ float ftanh(float x) {
    x = fminf(fmaxf(x, -15.f), 15.f);
    float t = __expf(-2.f * x);
    return __fdividef(1.f - t, 1.f + t);
}

// ---------------------------------------------------------------------------
// One-time fp16 conversion
// ---------------------------------------------------------------------------
#define NX    ((size_t)MROWS * DIN)
#define NWIH1 ((size_t)G4H * DIN)
#define NWHH1 ((size_t)G4H * Hsz)
#define NCVT  (NX + 2 * NWIH1 + 2 * NWHH1)
__global__ __launch_bounds__(256) void convert_kernel(
    const float* __restrict__ X,
    const float* __restrict__ Wihf, const float* __restrict__ Wihb,
    const float* __restrict__ Whhf, const float* __restrict__ Whhb)
{
    size_t base = ((size_t)blockIdx.x * 256 + threadIdx.x) * 8;
    const float* src;
    __half* dst;
    if (base < NX)                        { src = X + base;                         dst = g_X_h + base; }
    else if (base < NX + NWIH1)           { size_t o = base - NX;                   src = Wihf + o; dst = g_Wih_h + o; }
    else if (base < NX + 2 * NWIH1)       { size_t o = base - NX - NWIH1;           src = Wihb + o; dst = g_Wih_h + NWIH1 + o; }
    else if (base < NX + 2*NWIH1 + NWHH1) { size_t o = base - NX - 2*NWIH1;         src = Whhf + o; dst = g_Whh_h[0] + o; }
    else                                  { size_t o = base - NX - 2*NWIH1 - NWHH1; src = Whhb + o; dst = g_Whh_h[1] + o; }
    float4 v0 = ((const float4*)src)[0];
    float4 v1 = ((const float4*)src)[1];
    __half2 h0 = __floats2half2_rn(v0.x, v0.y);
    __half2 h1 = __floats2half2_rn(v0.z, v0.w);
    __half2 h2 = __floats2half2_rn(v1.x, v1.y);
    __half2 h3 = __floats2half2_rn(v1.z, v1.w);
    uint4 u;
    u.x = *(uint32_t*)&h0; u.y = *(uint32_t*)&h1;
    u.z = *(uint32_t*)&h2; u.w = *(uint32_t*)&h3;
    *(uint4*)dst = u;
}

// ---------------------------------------------------------------------------
// Phase 1: G = X @ [Wf|Wb]^T + bias, fp16 MMA, 128x128, 4-stage (unchanged)
// ---------------------------------------------------------------------------
#define P1ST    40
#define P1STAGE (128 * P1ST)
#define P1DYN   (8 * P1STAGE * 2)

__global__ __launch_bounds__(256) void gemm_x_mma(
    const float* __restrict__ bihf, const float* __restrict__ bhhf,
    const float* __restrict__ bihb, const float* __restrict__ bhhb)
{
    extern __shared__ __half p1s[];
    __half* asb = p1s;
    __half* bsb = p1s + 4 * P1STAGE;

    const int n0  = blockIdx.x * 128;
    const int m0  = blockIdx.y * 128;
    const int tid = threadIdx.x;
    const int wid = tid >> 5, lane = tid & 31;
    const int warp_m = wid & 1, warp_n = wid >> 1;
    const int groupID = lane >> 2, tig = lane & 3;

    const int i0 = tid * 2, i1 = tid * 2 + 1;
    const int r0l = i0 >> 2, u0l = (i0 & 3) << 3;
    const int r1l = i1 >> 2, u1l = (i1 & 3) << 3;
    const __half* At0 = g_X_h   + (size_t)(m0 + r0l) * DIN + u0l;
    const __half* At1 = g_X_h   + (size_t)(m0 + r1l) * DIN + u1l;
    const __half* Bt0 = g_Wih_h + (size_t)(n0 + r0l) * DIN + u0l;
    const __half* Bt1 = g_Wih_h + (size_t)(n0 + r1l) * DIN + u1l;

    float acc[4][4][4];
#pragma unroll
    for (int mf = 0; mf < 4; mf++)
#pragma unroll
        for (int nf = 0; nf < 4; nf++)
#pragma unroll
            for (int i = 0; i < 4; i++) acc[mf][nf][i] = 0.f;

#define P1_LOAD(st, c)                                                \
    { int k0 = (c) * 32;                                              \
      cp16(&asb[(st) * P1STAGE + r0l * P1ST + u0l], At0 + k0);        \
      cp16(&asb[(st) * P1STAGE + r1l * P1ST + u1l], At1 + k0);        \
      cp16(&bsb[(st) * P1STAGE + r0l * P1ST + u0l], Bt0 + k0);        \
      cp16(&bsb[(st) * P1STAGE + r1l * P1ST + u1l], Bt1 + k0);        \
      CP_COMMIT(); }

    P1_LOAD(0, 0) P1_LOAD(1, 1) P1_LOAD(2, 2)
    const int NIT = DIN / 32;
    for (int it = 0; it < NIT; it++) {
        CP_WAIT2();
        __syncthreads();
        if (it + 3 < NIT) P1_LOAD((it + 3) & 3, it + 3)
        else              CP_COMMIT();
        const __half* A = asb + (it & 3) * P1STAGE;
        const __half* B = bsb + (it & 3) * P1STAGE;
#pragma unroll
        for (int ks = 0; ks < 2; ks++) {
            const int kk = ks * 16;
            uint32_t av[4][4], bv[4][2];
#pragma unroll
            for (int mf = 0; mf < 4; mf++) {
                int row = warp_m * 64 + mf * 16 + groupID;
                const uint32_t* ap  = (const uint32_t*)(A + row * P1ST + kk + 2 * tig);
                const uint32_t* ap2 = (const uint32_t*)(A + (row + 8) * P1ST + kk + 2 * tig);
                av[mf][0] = ap[0];  av[mf][2] = ap[4];
                av[mf][1] = ap2[0]; av[mf][3] = ap2[4];
            }
#pragma unroll
            for (int nf = 0; nf < 4; nf++) {
                int n = warp_n * 32 + nf * 8 + groupID;
                const uint32_t* bp = (const uint32_t*)(B + n * P1ST + kk + 2 * tig);
                bv[nf][0] = bp[0];
                bv[nf][1] = bp[4];
            }
#pragma unroll
            for (int mf = 0; mf < 4; mf++)
#pragma unroll
                for (int nf = 0; nf < 4; nf++)
                    mma_f16(acc[mf][nf], av[mf], bv[nf]);
        }
    }

#pragma unroll
    for (int nf = 0; nf < 4; nf++) {
        int c0 = warp_n * 32 + nf * 8 + 2 * tig;
        int n  = n0 + c0;
        float bias0, bias1;
        if (n < G4H) { bias0 = bihf[n] + bhhf[n]; bias1 = bihf[n + 1] + bhhf[n + 1]; }
        else         { bias0 = bihb[n - G4H] + bhhb[n - G4H];
                       bias1 = bihb[n + 1 - G4H] + bhhb[n + 1 - G4H]; }
#pragma unroll
        for (int mf = 0; mf < 4; mf++) {
            int r0 = m0 + warp_m * 64 + mf * 16 + groupID;
            __half2 v0 = __floats2half2_rn(acc[mf][nf][0] + bias0, acc[mf][nf][1] + bias1);
            __half2 v1 = __floats2half2_rn(acc[mf][nf][2] + bias0, acc[mf][nf][3] + bias1);
            *(__half2*)&g_G16[(size_t)r0 * NTOT + n]       = v0;
            *(__half2*)&g_G16[(size_t)(r0 + 8) * NTOT + n] = v1;
        }
    }
}

// ---------------------------------------------------------------------------
// Phase 2: PERSISTENT LSTM, warp-specialized producer + chunk-flag dataflow.
// 128 CTAs, 288 threads: warps 0-7 compute, warp 8 = DMA producer.
// No grid barrier: per-(dir,chunk,slice) flags gate the h DMA.
// ---------------------------------------------------------------------------
#define WROWB  2064
#define WBYTES (64 * WROWB)
#define HCHB   33024
#define HOFF   WBYTES
#define GTOFF  (HOFF + 2 * HCHB)
#define GXOFF  (GTOFF + 4 * 16 * 68 * 4)
#define P2DYN  (GXOFF + 64 * 72 * 2)

__global__ __launch_bounds__(288, 1) void lstm_persist(float* __restrict__ out)
{
    extern __shared__ char smraw[];
    __half* ws  = (__half*)smraw;
    float*  Gt  = (float*)(smraw + GTOFF);
    __half* gxs = (__half*)(smraw + GXOFF);
    __shared__ __align__(8) uint64_t s_mbar[4];   // full0, full1, cons0, cons1

    const uint32_t sm0  = smem_u32(smraw);
    const uint32_t hbu0 = sm0 + HOFF;
    const uint32_t hbu1 = sm0 + HOFF + HCHB;
    const uint32_t wsu  = sm0;
    const uint32_t mbF0 = smem_u32(&s_mbar[0]);
    const uint32_t mbF1 = smem_u32(&s_mbar[1]);
    const uint32_t mbC0 = smem_u32(&s_mbar[2]);
    const uint32_t mbC1 = smem_u32(&s_mbar[3]);

    const int bid   = blockIdx.x;
    const int dir   = bid >> 6;
    const int slice = bid & 63;
    const int hb    = slice << 4;
    const int tid   = threadIdx.x;
    const int wid   = tid >> 5, lane = tid & 31;

    if (tid == 0) {
        mbar_init(mbF0, 1);   mbar_init(mbF1, 1);
        mbar_init(mbC0, 256); mbar_init(mbC1, 256);
    }

    // ---- W slice resident load (once, compute threads only) ----
    if (tid < 256) {
        int r = tid >> 2, u = (tid & 3) << 3;
        int wrow = ((r >> 4) << 10) + hb + (r & 15);
        const __half* src = g_Whh_h[dir] + (size_t)wrow * Hsz;
#pragma unroll
        for (int i = 0; i < 32; i++)
            cp16(&ws[r * 1032 + u + i * 32], src + u + i * 32);
        CP_COMMIT();
        CP_WAIT0();
    }
    __syncthreads();   // all 288

    if (wid < 8) {
        // =================== COMPUTE WARPS ===================
        const int grp = wid >> 1;
        const int nw  = wid & 1;
        const int groupID = lane >> 2, tig = lane & 3;

        const uint32_t a_lane  = (uint32_t)((lane & 15) * WROWB + ((lane >> 4) << 4));
        const uint32_t b_lane0 = (uint32_t)((nw * 32 + (lane & 15)) * WROWB + ((lane >> 4) << 4));
        const uint32_t kgrp_b  = (uint32_t)(grp * 512);

        const int o0 = tid * 2, o1 = tid * 2 + 1;
        const int bl = tid >> 4, j = tid & 15;

        float cv[4];
#pragma unroll
        for (int q = 0; q < 4; q++) cv[q] = 0.f;

        for (int s = 0; s < Tlen; s++) {
            const int par  = s & 1;
            const int t_in = dir ? (Tlen - 1 - s) : s;

            // gate-x tile -> smem
            {
                int b0 = o0 >> 3, g0 = (o0 >> 1) & 3, f0 = o0 & 1;
                int b1 = o1 >> 3, g1 = (o1 >> 1) & 3, f1 = o1 & 1;
                cp16(&gxs[b0 * 72 + g0 * 16 + f0 * 8],
                     g_G16 + ((size_t)b0 * Tlen + t_in) * NTOT + dir * G4H + g0 * 1024 + hb + f0 * 8);
                cp16(&gxs[b1 * 72 + g1 * 16 + f1 * 8],
                     g_G16 + ((size_t)b1 * Tlen + t_in) * NTOT + dir * G4H + g1 * 1024 + hb + f1 * 8);
                CP_COMMIT();
            }

            for (int sub = 0; sub < 4; sub++) {
                const int buf = sub & 1;
                const int f   = s * 2 + (sub >> 1);
                mbar_wait(buf ? mbF1 : mbF0, f & 1);

                float acc[4][4];
#pragma unroll
                for (int nf = 0; nf < 4; nf++)
#pragma unroll
                    for (int i = 0; i < 4; i++) acc[nf][i] = 0.f;

                const uint32_t ab = (buf ? hbu1 : hbu0) + a_lane + kgrp_b;
                const uint32_t bb = wsu + b_lane0 + kgrp_b;
#pragma unroll
                for (int ks = 0; ks < 16; ks++) {
                    uint32_t a[4], b0r[4], b1r[4];
                    LDSM4(a[0], a[1], a[2], a[3], ab + ks * 32);
                    LDSM4(b0r[0], b0r[1], b0r[2], b0r[3], bb + ks * 32);
                    LDSM4(b1r[0], b1r[1], b1r[2], b1r[3], bb + 16 * WROWB + ks * 32);
                    uint32_t p0[2] = { b0r[0], b0r[2] }, p1[2] = { b0r[1], b0r[3] };
                    uint32_t p2[2] = { b1r[0], b1r[2] }, p3[2] = { b1r[1], b1r[3] };
                    mma_f16(acc[0], a, p0);
                    mma_f16(acc[1], a, p1);
                    mma_f16(acc[2], a, p2);
                    mma_f16(acc[3], a, p3);
                }
                mbar_arrive(buf ? mbC1 : mbC0);   // buffer consumed

#pragma unroll
                for (int nf = 0; nf < 4; nf++) {
                    int col = nw * 32 + nf * 8 + 2 * tig;
                    float* q0 = &Gt[(grp * 16 + groupID) * 68 + col];
                    float* q1 = &Gt[(grp * 16 + groupID + 8) * 68 + col];
                    q0[0] = acc[nf][0]; q0[1] = acc[nf][1];
                    q1[0] = acc[nf][2]; q1[1] = acc[nf][3];
                }
                if (sub == 0) CP_WAIT0();
                BAR1();

                {
                    int b = sub * 16 + bl;
                    int h = hb + j;
                    float gi = 0.f, gf = 0.f, gg = 0.f, go = 0.f;
#pragma unroll
                    for (int g4 = 0; g4 < 4; g4++) {
                        const float* gr = &Gt[(g4 * 16 + bl) * 68];
                        gi += gr[j];
                        gf += gr[16 + j];
                        gg += gr[32 + j];
                        go += gr[48 + j];
                    }
                    const __half* gx = &gxs[b * 72];
                    gi += __half2float(gx[j]);
                    gf += __half2float(gx[16 + j]);
                    gg += __half2float(gx[32 + j]);
                    go += __half2float(gx[48 + j]);

                    float si = fsig(gi);
                    float sf = fsig(gf);
                    float so = fsig(go);
                    float tg = ftanh(gg);

                    float cn = sf * cv[sub] + si * tg;
                    cv[sub] = cn;
                    float hn = so * ftanh(cn);
                    g_h_half[par ^ 1][dir][b * Hsz + h] = __float2half_rn(hn);
                    out[((size_t)b * Tlen + s) * (2 * Hsz) + dir * Hsz + h] = hn;
                    if (s == Tlen - 1) {
                        g_hT[dir][b * Hsz + h] = hn;
                        g_cT[dir][b * Hsz + h] = cn;
                    }
                }
                BAR1();

                if (tid == 0) {
                    asm volatile("fence.proxy.async;" ::: "memory");
                    unsigned* fl = &g_flags[((dir * 4 + sub) * 64 + slice) * 8];
                    asm volatile("st.release.gpu.u32 [%0], %1;"
                                 :: "l"(fl), "r"((unsigned)(s + 1)) : "memory");
                }
            }
        }
    } else {
        // =================== PRODUCER WARP (wid == 8) ===================
        for (int s = 0; s < Tlen; s++) {
            const __half* Ht = g_h_half[s & 1][dir];
            for (int c = 0; c < 4; c++) {
                const int b  = c & 1;
                const int fb = s * 2 + (c >> 1);     // per-buffer fill index
                if (fb >= 1) mbar_wait(b ? mbC1 : mbC0, (fb - 1) & 1);
                if (s > 0) {
                    const unsigned tgt = (unsigned)s;
                    const unsigned* p0 = &g_flags[((dir * 4 + c) * 64 + lane) * 8];
                    const unsigned* p1 = &g_flags[((dir * 4 + c) * 64 + 32 + lane) * 8];
                    unsigned v0, v1;
                    do {
                        asm volatile("ld.acquire.gpu.u32 %0, [%1];" : "=r"(v0) : "l"(p0) : "memory");
                        asm volatile("ld.acquire.gpu.u32 %0, [%1];" : "=r"(v1) : "l"(p1) : "memory");
                    } while (v0 < tgt || v1 < tgt);
                    __syncwarp();
                }
                if (lane == 0) {
                    asm volatile("fence.acq_rel.gpu;" ::: "memory");
                    uint32_t mb  = b ? mbF1 : mbF0;
                    uint32_t dst = b ? hbu1 : hbu0;
                    mbar_expect(mb, 32768u);
#pragma unroll
                    for (int r = 0; r < 16; r++)
                        bulk_g2s(dst + r * WROWB, Ht + (size_t)(c * 16 + r) * Hsz, 2048u, mb);
                }
            }
        }
    }
}

// ---------------------------------------------------------------------------
// Phase 3: decoder-init projections
// ---------------------------------------------------------------------------
__global__ __launch_bounds__(128) void proj_kernel(
    const float* __restrict__ fhW, const float* __restrict__ fhb,
    const float* __restrict__ fcW, const float* __restrict__ fcb,
    float* __restrict__ out2)
{
    __shared__ float As[64][17];
    __shared__ float Bs[64][17];

    const int which = blockIdx.y;
    const float* __restrict__ W    = which ? fcW : fhW;
    const float* __restrict__ bias = which ? fcb : fhb;
    const float* __restrict__ src0 = which ? g_cT[0] : g_hT[0];
    const float* __restrict__ src1 = which ? g_cT[1] : g_hT[1];

    const int d0  = blockIdx.x * 64;
    const int tid = threadIdx.x;
    const int ty  = tid >> 4;
    const int tx  = tid & 15;

    float acc[8][4];
#pragma unroll
    for (int r = 0; r < 8; r++)
#pragma unroll
        for (int c = 0; c < 4; c++) acc[r][c] = 0.f;

    for (int k0 = 0; k0 < 2 * Hsz; k0 += 16) {
#pragma unroll
        for (int i = 0; i < 2; i++) {
            int idx = tid * 2 + i;
            int row = idx >> 2;
            int c4  = (idx & 3) << 2;
            int k   = k0 + c4;
            const float* sp = (k < Hsz) ? &src0[row * Hsz + k]
                                        : &src1[row * Hsz + k - Hsz];
            float4 v = *(const float4*)sp;
            As[row][c4 + 0] = v.x; As[row][c4 + 1] = v.y;
            As[row][c4 + 2] = v.z; As[row][c4 + 3] = v.w;

            float4 w = *(const float4*)&W[(size_t)(d0 + row) * (2 * Hsz) + k0 + c4];
            Bs[row][c4 + 0] = w.x; Bs[row][c4 + 1] = w.y;
            Bs[row][c4 + 2] = w.z; Bs[row][c4 + 3] = w.w;
        }
        __syncthreads();
#pragma unroll
        for (int kk = 0; kk < 16; kk++) {
            float a[8], b[4];
#pragma unroll
            for (int r = 0; r < 8; r++) a[r] = As[ty * 8 + r][kk];
#pragma unroll
            for (int c = 0; c < 4; c++) b[c] = Bs[tx + 16 * c][kk];
#pragma unroll
            for (int r = 0; r < 8; r++)
#pragma unroll
                for (int c = 0; c < 4; c++) acc[r][c] += a[r] * b[c];
        }
        __syncthreads();
    }

#pragma unroll
    for (int c = 0; c < 4; c++) {
        int d = d0 + tx + 16 * c;
        float bv = bias[d];
#pragma unroll
        for (int r = 0; r < 8; r++) {
            int b = ty * 8 + r;
            out2[(size_t)which * (Bsz * Hsz) + b * Hsz + d] = tanhf(acc[r][c] + bv);
        }
    }
}

// ---------------------------------------------------------------------------
// Launch
// ---------------------------------------------------------------------------
extern "C" void kernel_launch(void* const* d_in, const int* in_sizes, int n_in,
                              void* d_out, int out_size)
{
    const float* X    = (const float*)d_in[0];
    const float* Wihf = (const float*)d_in[1];
    const float* Whhf = (const float*)d_in[2];
    const float* bihf = (const float*)d_in[3];
    const float* bhhf = (const float*)d_in[4];
    const float* Wihb = (const float*)d_in[5];
    const float* Whhb = (const float*)d_in[6];
    const float* bihb = (const float*)d_in[7];
    const float* bhhb = (const float*)d_in[8];
    const float* fcW  = (const float*)d_in[9];
    const float* fcb  = (const float*)d_in[10];
    const float* fhW  = (const float*)d_in[11];
    const float* fhb  = (const float*)d_in[12];
    float* out = (float*)d_out;

    cudaFuncSetAttribute(gemm_x_mma,
                         cudaFuncAttributeMaxDynamicSharedMemorySize, P1DYN);
    cudaFuncSetAttribute(lstm_persist,
                         cudaFuncAttributeMaxDynamicSharedMemorySize, P2DYN);

    zero_state_kernel<<<(Bsz * Hsz + 255) / 256, 256>>>();

    convert_kernel<<<(unsigned)(NCVT / 8 / 256), 256>>>(X, Wihf, Wihb, Whhf, Whhb);

    gemm_x_mma<<<dim3(NTOT / 128, MROWS / 128), 256, P1DYN>>>(bihf, bhhf, bihb, bhhb);

    lstm_persist<<<128, 288, P2DYN>>>(out);

    proj_kernel<<<dim3(Hsz / 64, 2), 128>>>(
        fhW, fhb, fcW, fcb, out + (size_t)Bsz * Tlen * 2 * Hsz);
}